// round 2
// baseline (speedup 1.0000x reference)
#include <cuda_runtime.h>
#include <math.h>

#define Bn    16384
#define KINd  1024
#define MINd  64
#define Sd    256
#define Td    128
#define H1d   128
#define H2d   64

// ------------------------- scratch (device globals; no allocs) --------------
static __device__ __align__(16) float g_P[Sd * Sd];
static __device__ __align__(16) float g_Q[Sd * Sd];
static __device__ __align__(16) float g_seeds[8 * Sd];
static __device__ __align__(16) float g_M[Td * MINd];
static __device__ __align__(16) float g_h1[(size_t)Bn * 2 * H1d];   // 16 MB
static __device__ __align__(16) float g_h2[(size_t)Bn * 2 * H2d];   // 8 MB
static __device__ __align__(16) float g_inner[(size_t)Bn * 2];
static __device__ float g_sWb[2 * H2d];
static __device__ float g_sbb[2];

__device__ __forceinline__ float sp_fast(float v) {
    float r = __logf(1.f + __expf(v));
    return (v > 20.f) ? v : r;
}

// ------------------------- 256x256 fp32 GEMM (A powers) ---------------------
__global__ void mm256_kernel(const float* __restrict__ A,
                             const float* __restrict__ Bm,
                             float* __restrict__ C) {
    __shared__ float As[16][16];
    __shared__ float Bs[16][17];
    int tx = threadIdx.x, ty = threadIdx.y;
    int row = blockIdx.y * 16 + ty;
    int col = blockIdx.x * 16 + tx;
    float acc = 0.f;
    for (int k0 = 0; k0 < Sd; k0 += 16) {
        As[ty][tx] = A[(size_t)row * Sd + k0 + tx];
        Bs[ty][tx] = Bm[(size_t)(k0 + ty) * Sd + col];
        __syncthreads();
#pragma unroll
        for (int kk = 0; kk < 16; ++kk) acc += As[ty][kk] * Bs[kk][tx];
        __syncthreads();
    }
    C[(size_t)row * Sd + col] = acc;
}

// seeds[p] = (A^16)^p c,  c = C_ssm^T
__global__ void seeds_kernel(const float* __restrict__ A16,
                             const float* __restrict__ Cssm) {
    __shared__ float w[Sd];
    int t = threadIdx.x;
    w[t] = Cssm[t];
    g_seeds[t] = w[t];
    __syncthreads();
    for (int p = 1; p < 8; ++p) {
        const float* arow = A16 + (size_t)t * Sd;
        float acc = 0.f;
#pragma unroll 8
        for (int j = 0; j < Sd; ++j) acc += arow[j] * w[j];
        __syncthreads();
        w[t] = acc;
        g_seeds[p * Sd + t] = acc;
        __syncthreads();
    }
}

// 8 parallel chains of 16 steps: M[tau][m] = B[m,:].v ; v <- A v
__global__ void __launch_bounds__(256) chains_kernel(const float* __restrict__ A,
                                                     const float* __restrict__ Bssm) {
    __shared__ float d[Sd];
    __shared__ float nd[Sd];
    int t = threadIdx.x;
    int p = blockIdx.x;
    d[t] = g_seeds[p * Sd + t];
    __syncthreads();
    for (int k = 0; k < 16; ++k) {
        if (t < 64) {
            const float* br = Bssm + (size_t)t * Sd;
            float s = 0.f;
#pragma unroll 8
            for (int j = 0; j < Sd; ++j) s += br[j] * d[j];
            g_M[(127 - (16 * p + k)) * MINd + t] = s;
        }
        {
            const float* ar = A + (size_t)t * Sd;
            float s2 = 0.f;
#pragma unroll 8
            for (int j = 0; j < Sd; ++j) s2 += ar[j] * d[j];
            nd[t] = s2;
        }
        __syncthreads();
        d[t] = nd[t];
        __syncthreads();
    }
}

// out[b] = wm * <x_mamba[b], M>   (537 MB stream; DRAM bound)
__global__ void __launch_bounds__(512) mamba_reduce_kernel(const float* __restrict__ xm,
                                                           const float* __restrict__ wm,
                                                           float* __restrict__ out) {
    __shared__ float4 Ms[2048];
    int t = threadIdx.x;
    const float4* Mg = (const float4*)g_M;
    for (int q = t; q < 2048; q += 512) Ms[q] = Mg[q];
    __syncthreads();
    int warp = t >> 5, lane = t & 31;
    int b = blockIdx.x * 16 + warp;
    const float4* xr = (const float4*)(xm + (size_t)b * (Td * MINd));
    float acc = 0.f;
#pragma unroll 8
    for (int j = lane; j < 2048; j += 32) {
        float4 xv = xr[j];
        float4 mv = Ms[j];
        acc += xv.x * mv.x + xv.y * mv.y + xv.z * mv.z + xv.w * mv.w;
    }
#pragma unroll
    for (int o = 16; o > 0; o >>= 1) acc += __shfl_down_sync(0xffffffffu, acc, o);
    if (lane == 0) out[b] = wm[0] * acc;
}

// row-sums of in_wb (over i) and in_bb (bias-collapse)
__global__ void ksums_kernel(const float* __restrict__ wb,
                             const float* __restrict__ bb) {
    int r = blockIdx.x, lane = threadIdx.x;
    float s = 0.f;
    if (r < 128) {
        const float* row = wb + (size_t)r * KINd;
        for (int i = lane; i < KINd; i += 32) s += row[i];
    } else if (r < 130) {
        const float* row = bb + (size_t)(r - 128) * KINd;
        for (int i = lane; i < KINd; i += 32) s += row[i];
    }
#pragma unroll
    for (int o = 16; o > 0; o >>= 1) s += __shfl_down_sync(0xffffffffu, s, o);
    if (lane == 0) {
        if (r < 128) g_sWb[r] = s;
        else if (r < 130) g_sbb[r - 128] = s;
    }
}

// h1 = relu(x @ W1[u] + b1[u])
__global__ void __launch_bounds__(256) gemm1_kernel(const float* __restrict__ x,
                                                    const float* __restrict__ w1,
                                                    const float* __restrict__ b1) {
    __shared__ float xs[64][33];
    __shared__ float ws[32][128];
    const int u = blockIdx.x;
    const int b0 = blockIdx.y * 64;
    const int t = threadIdx.x;
    const int tx = t & 15;
    const int ty = t >> 4;
    const float* w1u = w1 + (size_t)u * KINd * H1d;

    float acc[4][8];
#pragma unroll
    for (int i = 0; i < 4; ++i)
#pragma unroll
        for (int j = 0; j < 8; ++j) acc[i][j] = 0.f;

    for (int k0 = 0; k0 < KINd; k0 += 32) {
        for (int q = t; q < 512; q += 256) {
            int r = q >> 3, c = q & 7;
            float4 v = *(const float4*)(x + (size_t)(b0 + r) * KINd + k0 + c * 4);
            xs[r][c * 4 + 0] = v.x; xs[r][c * 4 + 1] = v.y;
            xs[r][c * 4 + 2] = v.z; xs[r][c * 4 + 3] = v.w;
        }
        for (int q = t; q < 1024; q += 256) {
            int r = q >> 5, c = q & 31;
            *(float4*)&ws[r][c * 4] = *(const float4*)(w1u + (size_t)(k0 + r) * H1d + c * 4);
        }
        __syncthreads();
#pragma unroll 8
        for (int kk = 0; kk < 32; ++kk) {
            float a0 = xs[ty * 4 + 0][kk];
            float a1 = xs[ty * 4 + 1][kk];
            float a2 = xs[ty * 4 + 2][kk];
            float a3 = xs[ty * 4 + 3][kk];
            float4 w0 = *(float4*)&ws[kk][tx * 8];
            float4 w1v = *(float4*)&ws[kk][tx * 8 + 4];
            float wv[8] = {w0.x, w0.y, w0.z, w0.w, w1v.x, w1v.y, w1v.z, w1v.w};
#pragma unroll
            for (int j = 0; j < 8; ++j) {
                acc[0][j] += a0 * wv[j];
                acc[1][j] += a1 * wv[j];
                acc[2][j] += a2 * wv[j];
                acc[3][j] += a3 * wv[j];
            }
        }
        __syncthreads();
    }
#pragma unroll
    for (int i = 0; i < 4; ++i) {
        int b = b0 + ty * 4 + i;
#pragma unroll
        for (int j = 0; j < 8; ++j) {
            int n = tx * 8 + j;
            float v = acc[i][j] + b1[u * H1d + n];
            g_h1[((size_t)b * 2 + u) * H1d + n] = fmaxf(v, 0.f);
        }
    }
}

// h2 = relu(h1 @ W2[u] + b2[u])
__global__ void __launch_bounds__(256) gemm2_kernel(const float* __restrict__ w2,
                                                    const float* __restrict__ b2) {
    __shared__ float hs[64][65];
    __shared__ float w2s[64][64];
    const int u = blockIdx.x;
    const int b0 = blockIdx.y * 64;
    const int t = threadIdx.x;
    const int tx = t & 15;
    const int ty = t >> 4;
    const float* w2u = w2 + (size_t)u * H1d * H2d;

    float acc[4][4];
#pragma unroll
    for (int i = 0; i < 4; ++i)
#pragma unroll
        for (int j = 0; j < 4; ++j) acc[i][j] = 0.f;

    for (int k0 = 0; k0 < H1d; k0 += 64) {
        for (int q = t; q < 1024; q += 256) {
            int r = q >> 4, c = q & 15;
            float4 v = *(const float4*)(g_h1 + ((size_t)(b0 + r) * 2 + u) * H1d + k0 + c * 4);
            hs[r][c * 4 + 0] = v.x; hs[r][c * 4 + 1] = v.y;
            hs[r][c * 4 + 2] = v.z; hs[r][c * 4 + 3] = v.w;
        }
        for (int q = t; q < 1024; q += 256) {
            int r = q >> 4, c = q & 15;
            *(float4*)&w2s[r][c * 4] = *(const float4*)(w2u + (size_t)(k0 + r) * H2d + c * 4);
        }
        __syncthreads();
#pragma unroll 8
        for (int f = 0; f < 64; ++f) {
            float4 w = *(float4*)&w2s[f][tx * 4];
            float a0 = hs[ty * 4 + 0][f];
            float a1 = hs[ty * 4 + 1][f];
            float a2 = hs[ty * 4 + 2][f];
            float a3 = hs[ty * 4 + 3][f];
            acc[0][0] += a0 * w.x; acc[0][1] += a0 * w.y; acc[0][2] += a0 * w.z; acc[0][3] += a0 * w.w;
            acc[1][0] += a1 * w.x; acc[1][1] += a1 * w.y; acc[1][2] += a1 * w.z; acc[1][3] += a1 * w.w;
            acc[2][0] += a2 * w.x; acc[2][1] += a2 * w.y; acc[2][2] += a2 * w.z; acc[2][3] += a2 * w.w;
            acc[3][0] += a3 * w.x; acc[3][1] += a3 * w.y; acc[3][2] += a3 * w.z; acc[3][3] += a3 * w.w;
        }
        __syncthreads();
    }
#pragma unroll
    for (int i = 0; i < 4; ++i) {
        int b = b0 + ty * 4 + i;
#pragma unroll
        for (int j = 0; j < 4; ++j) {
            int g = tx * 4 + j;
            float v = acc[i][j] + b2[u * H2d + g];
            g_h2[((size_t)b * 2 + u) * H2d + g] = fmaxf(v, 0.f);
        }
    }
}

// inner[b,u] = sum_i softplus(h2.Ww[:,i]+bw[i])*x[b,i] + h2.sWb + sbb
__global__ void __launch_bounds__(256) stage2_kernel(const float* __restrict__ x,
                                                     const float* __restrict__ ww,
                                                     const float* __restrict__ bw) {
    __shared__ float h2s[64][64];
    __shared__ float wws[64][64];
    __shared__ float xsh[64][64];
    __shared__ float sWb_sh[64];
    const int u = blockIdx.x;
    const int b0 = blockIdx.y * 64;
    const int t = threadIdx.x;
    const int tx = t & 15;
    const int ty = t >> 4;
    const float* wwu = ww + (size_t)u * H2d * KINd;
    const float* bwu = bw + (size_t)u * KINd;

    if (t < 64) sWb_sh[t] = g_sWb[u * H2d + t];
    for (int q = t; q < 1024; q += 256) {
        int r = q >> 4, c = q & 15;
        *(float4*)&h2s[r][c * 4] =
            *(const float4*)(g_h2 + ((size_t)(b0 + r) * 2 + u) * H2d + c * 4);
    }
    __syncthreads();

    float part[4] = {0.f, 0.f, 0.f, 0.f};

    for (int it = 0; it < 16; ++it) {
        int i0 = it * 64;
        __syncthreads();
        for (int q = t; q < 1024; q += 256) {
            int r = q >> 4, c = q & 15;
            *(float4*)&wws[r][c * 4] = *(const float4*)(wwu + (size_t)r * KINd + i0 + c * 4);
        }
        for (int q = t; q < 1024; q += 256) {
            int r = q >> 4, c = q & 15;
            *(float4*)&xsh[r][c * 4] = *(const float4*)(x + (size_t)(b0 + r) * KINd + i0 + c * 4);
        }
        __syncthreads();

        float acc[4][4];
#pragma unroll
        for (int i = 0; i < 4; ++i)
#pragma unroll
            for (int j = 0; j < 4; ++j) acc[i][j] = 0.f;

#pragma unroll 8
        for (int g = 0; g < 64; ++g) {
            float4 w = *(float4*)&wws[g][tx * 4];
            float a0 = h2s[ty * 4 + 0][g];
            float a1 = h2s[ty * 4 + 1][g];
            float a2 = h2s[ty * 4 + 2][g];
            float a3 = h2s[ty * 4 + 3][g];
            acc[0][0] += a0 * w.x; acc[0][1] += a0 * w.y; acc[0][2] += a0 * w.z; acc[0][3] += a0 * w.w;
            acc[1][0] += a1 * w.x; acc[1][1] += a1 * w.y; acc[1][2] += a1 * w.z; acc[1][3] += a1 * w.w;
            acc[2][0] += a2 * w.x; acc[2][1] += a2 * w.y; acc[2][2] += a2 * w.z; acc[2][3] += a2 * w.w;
            acc[3][0] += a3 * w.x; acc[3][1] += a3 * w.y; acc[3][2] += a3 * w.z; acc[3][3] += a3 * w.w;
        }
#pragma unroll
        for (int j = 0; j < 4; ++j) {
            float bwv = bwu[i0 + tx * 4 + j];
#pragma unroll
            for (int bb = 0; bb < 4; ++bb) {
                float s = acc[bb][j] + bwv;
                part[bb] += sp_fast(s) * xsh[ty * 4 + bb][tx * 4 + j];
            }
        }
    }

    // reduce across tx (width-16 segments inside each warp)
#pragma unroll
    for (int bb = 0; bb < 4; ++bb) {
#pragma unroll
        for (int o = 8; o > 0; o >>= 1)
            part[bb] += __shfl_down_sync(0xffffffffu, part[bb], o, 16);
    }
    if (tx == 0) {
        float sbbv = g_sbb[u];
#pragma unroll
        for (int bb = 0; bb < 4; ++bb) {
            int row = ty * 4 + bb;
            float wbterm = 0.f;
#pragma unroll 8
            for (int g = 0; g < 64; ++g) wbterm += h2s[row][g] * sWb_sh[g];
            g_inner[(size_t)(b0 + row) * 2 + u] = part[bb] + wbterm + sbbv;
        }
    }
}

// outer MLP: out[b] += wk * kan_out[b]
__global__ void __launch_bounds__(128) outer_kernel(const float* __restrict__ ow1,
                                                    const float* __restrict__ ob1,
                                                    const float* __restrict__ ow2,
                                                    const float* __restrict__ ob2,
                                                    const float* __restrict__ oww,
                                                    const float* __restrict__ obw,
                                                    const float* __restrict__ owb,
                                                    const float* __restrict__ obb,
                                                    const float* __restrict__ wk,
                                                    float* __restrict__ out) {
    __shared__ float OW2s[128][64];
    __shared__ float w1as[128], w1bs[128], b1s[128];
    __shared__ float ob2s[64], owws[64], owbs[64];
    const int t = threadIdx.x;
    const int b = blockIdx.x * 128 + t;
    const float i0 = g_inner[(size_t)b * 2 + 0];
    const float i1 = g_inner[(size_t)b * 2 + 1];
    float kan = 0.f;

    for (int v = 0; v < 2; ++v) {
        __syncthreads();
        // ow1: [2,2,128]
        if (t < 128) {
            w1as[t] = ow1[(v * 2 + 0) * H1d + t];
            w1bs[t] = ow1[(v * 2 + 1) * H1d + t];
            b1s[t]  = ob1[v * H1d + t];
        }
        if (t < 64) {
            ob2s[t] = ob2[v * H2d + t];
            owws[t] = oww[v * H2d + t];   // [2,64,1]
            owbs[t] = owb[v * H2d + t];
        }
        for (int q = t; q < 2048; q += 128) {  // 128x16 float4
            int r = q >> 4, c = q & 15;
            *(float4*)&OW2s[r][c * 4] =
                *(const float4*)(ow2 + ((size_t)v * H1d + r) * H2d + c * 4);
        }
        __syncthreads();

        float g2a[64];
#pragma unroll
        for (int j = 0; j < 64; ++j) g2a[j] = ob2s[j];
        for (int f = 0; f < 128; ++f) {
            float g1f = fmaxf(i0 * w1as[f] + i1 * w1bs[f] + b1s[f], 0.f);
#pragma unroll
            for (int j = 0; j < 64; ++j) g2a[j] += g1f * OW2s[f][j];
        }
        float sw = 0.f, sb = 0.f;
#pragma unroll
        for (int j = 0; j < 64; ++j) {
            float g2v = fmaxf(g2a[j], 0.f);
            sw += g2v * owws[j];
            sb += g2v * owbs[j];
        }
        float wout = sp_fast(sw + obw[v]);
        float bout = sb + obb[v];
        kan += wout * (i0 + i1) + 2.f * bout;
    }
    out[b] += wk[0] * kan;
}

extern "C" void kernel_launch(void* const* d_in, const int* in_sizes, int n_in,
                              void* d_out, int out_size) {
    const float* x_kan   = (const float*)d_in[0];
    const float* x_mamba = (const float*)d_in[1];
    const float* in_w1 = (const float*)d_in[2];
    const float* in_b1 = (const float*)d_in[3];
    const float* in_w2 = (const float*)d_in[4];
    const float* in_b2 = (const float*)d_in[5];
    const float* in_ww = (const float*)d_in[6];
    const float* in_bw = (const float*)d_in[7];
    const float* in_wb = (const float*)d_in[8];
    const float* in_bb = (const float*)d_in[9];
    const float* out_w1 = (const float*)d_in[10];
    const float* out_b1 = (const float*)d_in[11];
    const float* out_w2 = (const float*)d_in[12];
    const float* out_b2 = (const float*)d_in[13];
    const float* out_ww = (const float*)d_in[14];
    const float* out_bw = (const float*)d_in[15];
    const float* out_wb = (const float*)d_in[16];
    const float* out_bb = (const float*)d_in[17];
    const float* A      = (const float*)d_in[18];
    const float* B_ssm  = (const float*)d_in[19];
    const float* C_ssm  = (const float*)d_in[20];
    const float* wk     = (const float*)d_in[21];
    const float* wm     = (const float*)d_in[22];
    float* out = (float*)d_out;

    float *gP, *gQ;
    cudaGetSymbolAddress((void**)&gP, g_P);
    cudaGetSymbolAddress((void**)&gQ, g_Q);

    dim3 b16(16, 16), g16(16, 16);
    // A^2, A^4, A^8, A^16 (ends in gQ)
    mm256_kernel<<<g16, b16>>>(A, A, gP);
    mm256_kernel<<<g16, b16>>>(gP, gP, gQ);
    mm256_kernel<<<g16, b16>>>(gQ, gQ, gP);
    mm256_kernel<<<g16, b16>>>(gP, gP, gQ);
    seeds_kernel<<<1, 256>>>(gQ, C_ssm);
    chains_kernel<<<8, 256>>>(A, B_ssm);
    mamba_reduce_kernel<<<Bn / 16, 512>>>(x_mamba, wm, out);

    ksums_kernel<<<130, 32>>>(in_wb, in_bb);
    gemm1_kernel<<<dim3(2, Bn / 64), 256>>>(x_kan, in_w1, in_b1);
    gemm2_kernel<<<dim3(2, Bn / 64), 256>>>(in_w2, in_b2);
    stage2_kernel<<<dim3(2, Bn / 64), 256>>>(x_kan, in_ww, in_bw);
    outer_kernel<<<Bn / 128, 128>>>(out_w1, out_b1, out_w2, out_b2,
                                    out_ww, out_bw, out_wb, out_bb, wk, out);
}

// round 3
// speedup vs baseline: 1.0269x; 1.0269x over previous
#include <cuda_runtime.h>
#include <math.h>

#define Bn    16384
#define KINd  1024
#define MINd  64
#define Sd    256
#define Td    128
#define H1d   128
#define H2d   64

typedef unsigned long long ull;

// ------------------------- scratch (device globals; no allocs) --------------
static __device__ __align__(16) float g_P[Sd * Sd];
static __device__ __align__(16) float g_Q[Sd * Sd];
static __device__ __align__(16) float g_seeds[8 * Sd];
static __device__ __align__(16) float g_M[Td * MINd];
static __device__ __align__(16) float g_h1[(size_t)Bn * 2 * H1d];   // 16 MB
static __device__ __align__(16) float g_h2[(size_t)Bn * 2 * H2d];   // 8 MB
static __device__ __align__(16) float g_inner[(size_t)Bn * 2];
static __device__ float g_sWb[2 * H2d];
static __device__ float g_sbb[2];

__device__ __forceinline__ float sp_fast(float v) {
    float r = __logf(1.f + __expf(v));
    return (v > 20.f) ? v : r;
}

// ---- packed f32x2 helpers ---------------------------------------------------
__device__ __forceinline__ void ffma2(ull& d, ull a, ull b) {
    asm("fma.rn.f32x2 %0, %1, %2, %0;" : "+l"(d) : "l"(a), "l"(b));
}
__device__ __forceinline__ void add2(ull& d, ull o) {
    asm("add.rn.f32x2 %0, %0, %1;" : "+l"(d) : "l"(o));
}
__device__ __forceinline__ ull pack2(float lo, float hi) {
    ull r; asm("mov.b64 %0, {%1, %2};" : "=l"(r) : "f"(lo), "f"(hi)); return r;
}
__device__ __forceinline__ void unpack2(ull v, float& lo, float& hi) {
    asm("mov.b64 {%0, %1}, %2;" : "=f"(lo), "=f"(hi) : "l"(v));
}

// ------------------------- 256x256 fp32 GEMM (A powers) ---------------------
__global__ void __launch_bounds__(256) mm256_kernel(const float* __restrict__ A,
                                                    const float* __restrict__ Bm,
                                                    float* __restrict__ C) {
    __shared__ float As[32][17];
    __shared__ float Bs[16][33];
    const int t = threadIdx.x;
    const int tx = t & 15, ty = t >> 4;
    const int rb = blockIdx.y * 32, cb = blockIdx.x * 32;
    float c00 = 0.f, c01 = 0.f, c10 = 0.f, c11 = 0.f;
    for (int k0 = 0; k0 < Sd; k0 += 16) {
        for (int q = t; q < 512; q += 256) {
            int r = q >> 4, c = q & 15;
            As[r][c] = A[(size_t)(rb + r) * Sd + k0 + c];
        }
        for (int q = t; q < 512; q += 256) {
            int r = q >> 5, c = q & 31;
            Bs[r][c] = Bm[(size_t)(k0 + r) * Sd + cb + c];
        }
        __syncthreads();
#pragma unroll
        for (int kk = 0; kk < 16; ++kk) {
            float a0 = As[ty * 2][kk], a1 = As[ty * 2 + 1][kk];
            float b0v = Bs[kk][tx * 2], b1v = Bs[kk][tx * 2 + 1];
            c00 += a0 * b0v; c01 += a0 * b1v;
            c10 += a1 * b0v; c11 += a1 * b1v;
        }
        __syncthreads();
    }
    C[(size_t)(rb + ty * 2) * Sd + cb + tx * 2]         = c00;
    C[(size_t)(rb + ty * 2) * Sd + cb + tx * 2 + 1]     = c01;
    C[(size_t)(rb + ty * 2 + 1) * Sd + cb + tx * 2]     = c10;
    C[(size_t)(rb + ty * 2 + 1) * Sd + cb + tx * 2 + 1] = c11;
}

// seeds[p] = (A^16)^p c,  c = C_ssm^T
__global__ void seeds_kernel(const float* __restrict__ A16,
                             const float* __restrict__ Cssm) {
    __shared__ float w[Sd];
    int t = threadIdx.x;
    w[t] = Cssm[t];
    g_seeds[t] = w[t];
    __syncthreads();
    for (int p = 1; p < 8; ++p) {
        const float* arow = A16 + (size_t)t * Sd;
        float acc = 0.f;
#pragma unroll 8
        for (int j = 0; j < Sd; ++j) acc += arow[j] * w[j];
        __syncthreads();
        w[t] = acc;
        g_seeds[p * Sd + t] = acc;
        __syncthreads();
    }
}

// 8 parallel chains of 16 steps: M[tau][m] = B[m,:].v ; v <- A v
__global__ void __launch_bounds__(256) chains_kernel(const float* __restrict__ A,
                                                     const float* __restrict__ Bssm) {
    __shared__ float d[Sd];
    __shared__ float nd[Sd];
    int t = threadIdx.x;
    int p = blockIdx.x;
    d[t] = g_seeds[p * Sd + t];
    __syncthreads();
    for (int k = 0; k < 16; ++k) {
        if (t < 64) {
            const float* br = Bssm + (size_t)t * Sd;
            float s = 0.f;
#pragma unroll 8
            for (int j = 0; j < Sd; ++j) s += br[j] * d[j];
            g_M[(127 - (16 * p + k)) * MINd + t] = s;
        }
        {
            const float* ar = A + (size_t)t * Sd;
            float s2 = 0.f;
#pragma unroll 8
            for (int j = 0; j < Sd; ++j) s2 += ar[j] * d[j];
            nd[t] = s2;
        }
        __syncthreads();
        d[t] = nd[t];
        __syncthreads();
    }
}

// out[b] = wm * <x_mamba[b], M>   (537 MB stream; DRAM bound)
__global__ void __launch_bounds__(512) mamba_reduce_kernel(const float* __restrict__ xm,
                                                           const float* __restrict__ wm,
                                                           float* __restrict__ out) {
    __shared__ float4 Ms[2048];
    int t = threadIdx.x;
    const float4* Mg = (const float4*)g_M;
    for (int q = t; q < 2048; q += 512) Ms[q] = Mg[q];
    __syncthreads();
    int warp = t >> 5, lane = t & 31;
    int b = blockIdx.x * 16 + warp;
    const float4* xr = (const float4*)(xm + (size_t)b * (Td * MINd));
    float acc = 0.f;
#pragma unroll 8
    for (int j = lane; j < 2048; j += 32) {
        float4 xv = xr[j];
        float4 mv = Ms[j];
        acc += xv.x * mv.x + xv.y * mv.y + xv.z * mv.z + xv.w * mv.w;
    }
#pragma unroll
    for (int o = 16; o > 0; o >>= 1) acc += __shfl_down_sync(0xffffffffu, acc, o);
    if (lane == 0) out[b] = wm[0] * acc;
}

// row-sums of in_wb (over i) and in_bb (bias-collapse)
__global__ void ksums_kernel(const float* __restrict__ wb,
                             const float* __restrict__ bb) {
    int r = blockIdx.x, lane = threadIdx.x;
    float s = 0.f;
    if (r < 128) {
        const float* row = wb + (size_t)r * KINd;
        for (int i = lane; i < KINd; i += 32) s += row[i];
    } else if (r < 130) {
        const float* row = bb + (size_t)(r - 128) * KINd;
        for (int i = lane; i < KINd; i += 32) s += row[i];
    }
#pragma unroll
    for (int o = 16; o > 0; o >>= 1) s += __shfl_down_sync(0xffffffffu, s, o);
    if (lane == 0) {
        if (r < 128) g_sWb[r] = s;
        else if (r < 130) g_sbb[r - 128] = s;
    }
}

// h1 = relu(x @ W1[u] + b1[u]) — 128x128 block tile, f32x2 packed math
__global__ void __launch_bounds__(256) gemm1_kernel(const float* __restrict__ x,
                                                    const float* __restrict__ w1,
                                                    const float* __restrict__ b1) {
    __shared__ float xs[128][36];
    __shared__ float ws[32][128];
    const int u = blockIdx.x;
    const int b0 = blockIdx.y * 128;
    const int t = threadIdx.x;
    const int tx = t & 15;   // 8 cols each (4 col-pairs)
    const int ty = t >> 4;   // 8 rows each
    const float* w1u = w1 + (size_t)u * KINd * H1d;
    const float* b1u = b1 + (size_t)u * H1d;

    ull acc2[8][4];
#pragma unroll
    for (int r = 0; r < 8; ++r)
#pragma unroll
        for (int j = 0; j < 4; ++j) acc2[r][j] = 0ULL;

    for (int k0 = 0; k0 < KINd; k0 += 32) {
        for (int q = t; q < 1024; q += 256) {
            int r = q >> 3, c = q & 7;
            *(float4*)&xs[r][c * 4] =
                *(const float4*)(x + (size_t)(b0 + r) * KINd + k0 + c * 4);
        }
        for (int q = t; q < 1024; q += 256) {
            int r = q >> 5, c = q & 31;
            *(float4*)&ws[r][c * 4] =
                *(const float4*)(w1u + (size_t)(k0 + r) * H1d + c * 4);
        }
        __syncthreads();
#pragma unroll 4
        for (int kk = 0; kk < 32; ++kk) {
            ull ap[8];
#pragma unroll
            for (int r = 0; r < 8; ++r) {
                float a = xs[ty * 8 + r][kk];
                ap[r] = pack2(a, a);
            }
            ulonglong2 wa = *(const ulonglong2*)&ws[kk][tx * 8];
            ulonglong2 wb = *(const ulonglong2*)&ws[kk][tx * 8 + 4];
#pragma unroll
            for (int r = 0; r < 8; ++r) {
                ffma2(acc2[r][0], ap[r], wa.x);
                ffma2(acc2[r][1], ap[r], wa.y);
                ffma2(acc2[r][2], ap[r], wb.x);
                ffma2(acc2[r][3], ap[r], wb.y);
            }
        }
        __syncthreads();
    }
#pragma unroll
    for (int r = 0; r < 8; ++r) {
        int b = b0 + ty * 8 + r;
        float* dst = g_h1 + ((size_t)b * 2 + u) * H1d + tx * 8;
#pragma unroll
        for (int j = 0; j < 4; ++j) {
            float lo, hi;
            unpack2(acc2[r][j], lo, hi);
            int n = tx * 8 + 2 * j;
            float v0 = fmaxf(lo + b1u[n], 0.f);
            float v1 = fmaxf(hi + b1u[n + 1], 0.f);
            float2 o2; o2.x = v0; o2.y = v1;
            *(float2*)(dst + 2 * j) = o2;
        }
    }
}

// h2 = relu(h1 @ W2[u] + b2[u])
__global__ void __launch_bounds__(256) gemm2_kernel(const float* __restrict__ w2,
                                                    const float* __restrict__ b2) {
    __shared__ float hs[64][65];
    __shared__ float w2s[64][64];
    const int u = blockIdx.x;
    const int b0 = blockIdx.y * 64;
    const int t = threadIdx.x;
    const int tx = t & 15;
    const int ty = t >> 4;
    const float* w2u = w2 + (size_t)u * H1d * H2d;

    float acc[4][4];
#pragma unroll
    for (int i = 0; i < 4; ++i)
#pragma unroll
        for (int j = 0; j < 4; ++j) acc[i][j] = 0.f;

    for (int k0 = 0; k0 < H1d; k0 += 64) {
        for (int q = t; q < 1024; q += 256) {
            int r = q >> 4, c = q & 15;
            float4 v = *(const float4*)(g_h1 + ((size_t)(b0 + r) * 2 + u) * H1d + k0 + c * 4);
            hs[r][c * 4 + 0] = v.x; hs[r][c * 4 + 1] = v.y;
            hs[r][c * 4 + 2] = v.z; hs[r][c * 4 + 3] = v.w;
        }
        for (int q = t; q < 1024; q += 256) {
            int r = q >> 4, c = q & 15;
            *(float4*)&w2s[r][c * 4] = *(const float4*)(w2u + (size_t)(k0 + r) * H2d + c * 4);
        }
        __syncthreads();
#pragma unroll 8
        for (int f = 0; f < 64; ++f) {
            float4 w = *(float4*)&w2s[f][tx * 4];
            float a0 = hs[ty * 4 + 0][f];
            float a1 = hs[ty * 4 + 1][f];
            float a2 = hs[ty * 4 + 2][f];
            float a3 = hs[ty * 4 + 3][f];
            acc[0][0] += a0 * w.x; acc[0][1] += a0 * w.y; acc[0][2] += a0 * w.z; acc[0][3] += a0 * w.w;
            acc[1][0] += a1 * w.x; acc[1][1] += a1 * w.y; acc[1][2] += a1 * w.z; acc[1][3] += a1 * w.w;
            acc[2][0] += a2 * w.x; acc[2][1] += a2 * w.y; acc[2][2] += a2 * w.z; acc[2][3] += a2 * w.w;
            acc[3][0] += a3 * w.x; acc[3][1] += a3 * w.y; acc[3][2] += a3 * w.z; acc[3][3] += a3 * w.w;
        }
        __syncthreads();
    }
#pragma unroll
    for (int i = 0; i < 4; ++i) {
        int b = b0 + ty * 4 + i;
#pragma unroll
        for (int j = 0; j < 4; ++j) {
            int g = tx * 4 + j;
            float v = acc[i][j] + b2[u * H2d + g];
            g_h2[((size_t)b * 2 + u) * H2d + g] = fmaxf(v, 0.f);
        }
    }
}

// inner[b,u] = sum_i softplus(h2.Ww[:,i]+bw[i])*x[b,i] + h2.sWb + sbb
// 128-row block tile, packed GEMM accumulation, scalar softplus epilogue.
__global__ void __launch_bounds__(256) stage2_kernel(const float* __restrict__ x,
                                                     const float* __restrict__ ww,
                                                     const float* __restrict__ bw) {
    extern __shared__ char sm[];
    float* h2tf = (float*)sm;              // [64][132] transposed h2
    float* wws  = h2tf + 64 * 132;         // [64][68]
    float* xsh  = wws + 64 * 68;           // [128][68]
    float* bws  = xsh + 128 * 68;          // [64]
    float* sWbs = bws + 64;                // [64]
    const int u = blockIdx.x;
    const int b0 = blockIdx.y * 128;
    const int t = threadIdx.x;
    const int tx = t & 15;   // 4 i-cols each
    const int ty = t >> 4;   // 8 rows each
    const float* wwu = ww + (size_t)u * H2d * KINd;
    const float* bwu = bw + (size_t)u * KINd;

    if (t < 64) sWbs[t] = g_sWb[u * H2d + t];
    // transposed load of h2 tile (rows <-> g)
    for (int q = t; q < 2048; q += 256) {
        int r = q & 127, gq = (q >> 7) * 4;
        float4 v = *(const float4*)(g_h2 + ((size_t)(b0 + r) * 2 + u) * H2d + gq);
        h2tf[(gq + 0) * 132 + r] = v.x;
        h2tf[(gq + 1) * 132 + r] = v.y;
        h2tf[(gq + 2) * 132 + r] = v.z;
        h2tf[(gq + 3) * 132 + r] = v.w;
    }
    __syncthreads();

    ull acc2[4][4];
    float part[8];
#pragma unroll
    for (int r = 0; r < 8; ++r) part[r] = 0.f;

    for (int it = 0; it < 16; ++it) {
        int i0 = it * 64;
        __syncthreads();
        for (int q = t; q < 1024; q += 256) {
            int r = q >> 4, c = q & 15;
            *(float4*)&wws[r * 68 + c * 4] =
                *(const float4*)(wwu + (size_t)r * KINd + i0 + c * 4);
        }
        for (int q = t; q < 2048; q += 256) {
            int r = q >> 4, c = q & 15;
            *(float4*)&xsh[r * 68 + c * 4] =
                *(const float4*)(x + (size_t)(b0 + r) * KINd + i0 + c * 4);
        }
        if (t < 16) *(float4*)&bws[t * 4] = *(const float4*)(bwu + i0 + t * 4);
        __syncthreads();

#pragma unroll
        for (int rp = 0; rp < 4; ++rp)
#pragma unroll
            for (int j = 0; j < 4; ++j) acc2[rp][j] = 0ULL;

#pragma unroll 4
        for (int g = 0; g < 64; ++g) {
            ulonglong2 ha = *(const ulonglong2*)(h2tf + g * 132 + ty * 8);
            ulonglong2 hb = *(const ulonglong2*)(h2tf + g * 132 + ty * 8 + 4);
            float4 wv = *(const float4*)&wws[g * 68 + tx * 4];
            ull w0 = pack2(wv.x, wv.x), w1p = pack2(wv.y, wv.y);
            ull w2p = pack2(wv.z, wv.z), w3p = pack2(wv.w, wv.w);
            ffma2(acc2[0][0], ha.x, w0); ffma2(acc2[0][1], ha.x, w1p);
            ffma2(acc2[0][2], ha.x, w2p); ffma2(acc2[0][3], ha.x, w3p);
            ffma2(acc2[1][0], ha.y, w0); ffma2(acc2[1][1], ha.y, w1p);
            ffma2(acc2[1][2], ha.y, w2p); ffma2(acc2[1][3], ha.y, w3p);
            ffma2(acc2[2][0], hb.x, w0); ffma2(acc2[2][1], hb.x, w1p);
            ffma2(acc2[2][2], hb.x, w2p); ffma2(acc2[2][3], hb.x, w3p);
            ffma2(acc2[3][0], hb.y, w0); ffma2(acc2[3][1], hb.y, w1p);
            ffma2(acc2[3][2], hb.y, w2p); ffma2(acc2[3][3], hb.y, w3p);
        }

#pragma unroll
        for (int j = 0; j < 4; ++j) {
            float bwv = bws[tx * 4 + j];
#pragma unroll
            for (int rp = 0; rp < 4; ++rp) {
                float s0, s1;
                unpack2(acc2[rp][j], s0, s1);
                float p0 = sp_fast(s0 + bwv);
                float p1 = sp_fast(s1 + bwv);
                part[2 * rp]     += p0 * xsh[(ty * 8 + 2 * rp) * 68 + tx * 4 + j];
                part[2 * rp + 1] += p1 * xsh[(ty * 8 + 2 * rp + 1) * 68 + tx * 4 + j];
            }
        }
    }

    // fold wbterm: each tx covers g in [tx*4, tx*4+4)
#pragma unroll
    for (int gg = 0; gg < 4; ++gg) {
        int g = tx * 4 + gg;
        float swv = sWbs[g];
#pragma unroll
        for (int r = 0; r < 8; ++r)
            part[r] += h2tf[g * 132 + ty * 8 + r] * swv;
    }
#pragma unroll
    for (int r = 0; r < 8; ++r)
#pragma unroll
        for (int o = 8; o > 0; o >>= 1)
            part[r] += __shfl_down_sync(0xffffffffu, part[r], o, 16);
    if (tx == 0) {
        float sbbv = g_sbb[u];
#pragma unroll
        for (int r = 0; r < 8; ++r)
            g_inner[(size_t)(b0 + ty * 8 + r) * 2 + u] = part[r] + sbbv;
    }
}

// outer MLP: out[b] += wk * kan_out[b]; thread = (b, v, f-half)
__global__ void __launch_bounds__(512) outer_kernel(const float* __restrict__ ow1,
                                                    const float* __restrict__ ob1,
                                                    const float* __restrict__ ow2,
                                                    const float* __restrict__ ob2,
                                                    const float* __restrict__ oww,
                                                    const float* __restrict__ obw,
                                                    const float* __restrict__ owb,
                                                    const float* __restrict__ obb,
                                                    const float* __restrict__ wk,
                                                    float* __restrict__ out) {
    extern __shared__ char sm[];
    float* OW2f = (float*)sm;   // [2][128][68]
    __shared__ float w1as[2][128], w1bs[2][128], b1s[2][128];
    __shared__ float ob2s[2][64], owws[2][64], owbs[2][64];
    const int t = threadIdx.x;
    const int bl = t >> 2;
    const int v = (t >> 1) & 1;
    const int hf = t & 1;
    const int b = blockIdx.x * 128 + bl;

    for (int q = t; q < 4096; q += 512) {   // 2*128*16 float4
        int vv = q >> 11, f = (q >> 4) & 127, c = q & 15;
        *(float4*)&OW2f[(vv * 128 + f) * 68 + c * 4] =
            *(const float4*)(ow2 + ((size_t)vv * 128 + f) * 64 + c * 4);
    }
    if (t < 256) {
        int vv = t >> 7, f = t & 127;
        w1as[vv][f] = ow1[(vv * 2 + 0) * 128 + f];
        w1bs[vv][f] = ow1[(vv * 2 + 1) * 128 + f];
        b1s[vv][f]  = ob1[vv * 128 + f];
    }
    if (t < 128) {
        int vv = t >> 6, j = t & 63;
        ob2s[vv][j] = ob2[vv * 64 + j];
        owws[vv][j] = oww[vv * 64 + j];
        owbs[vv][j] = owb[vv * 64 + j];
    }
    __syncthreads();

    const float i0 = g_inner[(size_t)b * 2 + 0];
    const float i1 = g_inner[(size_t)b * 2 + 1];

    ull g2a[32];
#pragma unroll
    for (int j = 0; j < 32; ++j)
        g2a[j] = (hf == 0) ? pack2(ob2s[v][2 * j], ob2s[v][2 * j + 1]) : 0ULL;

    const float* OW2v = OW2f + v * 128 * 68;
#pragma unroll 2
    for (int ff = 0; ff < 64; ++ff) {
        int f = hf * 64 + ff;
        float g1f = fmaxf(fmaf(i0, w1as[v][f], fmaf(i1, w1bs[v][f], b1s[v][f])), 0.f);
        ull g1p = pack2(g1f, g1f);
        const ull* row = (const ull*)(OW2v + f * 68);
#pragma unroll
        for (int j = 0; j < 32; ++j) ffma2(g2a[j], g1p, row[j]);
    }
    // combine f-halves
#pragma unroll
    for (int j = 0; j < 32; ++j) {
        ull o = __shfl_xor_sync(0xffffffffu, g2a[j], 1);
        add2(g2a[j], o);
    }
    float sw = 0.f, sb = 0.f;
#pragma unroll
    for (int j = 0; j < 32; ++j) {
        float a, c2;
        unpack2(g2a[j], a, c2);
        a = fmaxf(a, 0.f); c2 = fmaxf(c2, 0.f);
        sw += a * owws[v][2 * j] + c2 * owws[v][2 * j + 1];
        sb += a * owbs[v][2 * j] + c2 * owbs[v][2 * j + 1];
    }
    float wout = sp_fast(sw + obw[v]);
    float bout = sb + obb[v];
    float term = wout * (i0 + i1) + 2.f * bout;
    term += __shfl_xor_sync(0xffffffffu, term, 2);
    if ((t & 3) == 0) out[b] += wk[0] * term;
}

extern "C" void kernel_launch(void* const* d_in, const int* in_sizes, int n_in,
                              void* d_out, int out_size) {
    const float* x_kan   = (const float*)d_in[0];
    const float* x_mamba = (const float*)d_in[1];
    const float* in_w1 = (const float*)d_in[2];
    const float* in_b1 = (const float*)d_in[3];
    const float* in_w2 = (const float*)d_in[4];
    const float* in_b2 = (const float*)d_in[5];
    const float* in_ww = (const float*)d_in[6];
    const float* in_bw = (const float*)d_in[7];
    const float* in_wb = (const float*)d_in[8];
    const float* in_bb = (const float*)d_in[9];
    const float* out_w1 = (const float*)d_in[10];
    const float* out_b1 = (const float*)d_in[11];
    const float* out_w2 = (const float*)d_in[12];
    const float* out_b2 = (const float*)d_in[13];
    const float* out_ww = (const float*)d_in[14];
    const float* out_bw = (const float*)d_in[15];
    const float* out_wb = (const float*)d_in[16];
    const float* out_bb = (const float*)d_in[17];
    const float* A      = (const float*)d_in[18];
    const float* B_ssm  = (const float*)d_in[19];
    const float* C_ssm  = (const float*)d_in[20];
    const float* wk     = (const float*)d_in[21];
    const float* wm     = (const float*)d_in[22];
    float* out = (float*)d_out;

    float *gP, *gQ;
    cudaGetSymbolAddress((void**)&gP, g_P);
    cudaGetSymbolAddress((void**)&gQ, g_Q);

    const int S2SMEM = (64 * 132 + 64 * 68 + 128 * 68 + 64 + 64) * 4;   // 86528
    const int OSMEM  = 2 * 128 * 68 * 4;                                 // 69632
    cudaFuncSetAttribute(stage2_kernel, cudaFuncAttributeMaxDynamicSharedMemorySize, S2SMEM);
    cudaFuncSetAttribute(outer_kernel, cudaFuncAttributeMaxDynamicSharedMemorySize, OSMEM);

    // A^2, A^4, A^8, A^16 (ends in gQ)      launches 1-4
    mm256_kernel<<<dim3(8, 8), 256>>>(A, A, gP);
    mm256_kernel<<<dim3(8, 8), 256>>>(gP, gP, gQ);
    mm256_kernel<<<dim3(8, 8), 256>>>(gQ, gQ, gP);
    mm256_kernel<<<dim3(8, 8), 256>>>(gP, gP, gQ);
    ksums_kernel<<<130, 32>>>(in_wb, in_bb);                       // 5
    gemm1_kernel<<<dim3(2, Bn / 128), 256>>>(x_kan, in_w1, in_b1); // 6 (ncu -s 5 target)
    gemm2_kernel<<<dim3(2, Bn / 64), 256>>>(in_w2, in_b2);
    stage2_kernel<<<dim3(2, Bn / 128), 256, S2SMEM>>>(x_kan, in_ww, in_bw);
    seeds_kernel<<<1, 256>>>(gQ, C_ssm);
    chains_kernel<<<8, 256>>>(A, B_ssm);
    mamba_reduce_kernel<<<Bn / 16, 512>>>(x_mamba, wm, out);
    outer_kernel<<<Bn / 128, 512, OSMEM>>>(out_w1, out_b1, out_w2, out_b2,
                                           out_ww, out_bw, out_wb, out_bb, wk, out);
}

// round 4
// speedup vs baseline: 2.0780x; 2.0235x over previous
#include <cuda_runtime.h>
#include <math.h>

#define Bn    16384
#define KINd  1024
#define MINd  64
#define Sd    256
#define Td    128
#define H1d   128
#define H2d   64

typedef unsigned long long ull;

// ------------------------- scratch (device globals; no allocs) --------------
static __device__ __align__(16) float g_P[Sd * Sd];
static __device__ __align__(16) float g_Q[Sd * Sd];
static __device__ __align__(16) float g_seeds[8 * Sd];
static __device__ __align__(16) float g_M[Td * MINd];
static __device__ __align__(16) float g_h1[(size_t)Bn * 2 * H1d];   // 16 MB
static __device__ __align__(16) float g_h2[(size_t)Bn * 2 * H2d];   // 8 MB
static __device__ __align__(16) float g_inner[(size_t)Bn * 2];
static __device__ float g_sWb[2 * H2d];
static __device__ float g_sbb[2];

// ---- FMA-only softplus (no MUFU) -------------------------------------------
// softplus(s) = max(s,0) + log1p(exp(-|s|))
// exp via bit-trick + deg-5 poly; log1p via atanh series with Newton reciprocal.
__device__ __forceinline__ float sp_poly(float s) {
    float t = fmaxf(-fabsf(s), -17.f);          // exp(-17)=4e-8 -> negligible
    float z = t * 1.44269504f;
    int   ni = __float2int_rn(z);
    float f = z - (float)ni;                    // f in [-0.5, 0.5]
    float p = 1.33335581e-3f;
    p = fmaf(p, f, 9.61812911e-3f);
    p = fmaf(p, f, 5.55041087e-2f);
    p = fmaf(p, f, 2.40226507e-1f);
    p = fmaf(p, f, 6.93147181e-1f);
    p = fmaf(p, f, 1.f);
    float y = __int_as_float((ni + 127) << 23) * p;   // e^t in (0,1]
    // log1p(y): r = y/(2+y); ln(1+y) = 2*atanh(r)
    float v = 2.f + y;
    float r0 = fmaf(-0.1716f, v, 0.8249f);      // ~2.5% seed on [2,3]
    r0 = r0 * fmaf(-v, r0, 2.f);                // Newton 1
    r0 = r0 * fmaf(-v, r0, 2.f);                // Newton 2 (~4e-7 rel)
    float r  = y * r0;                           // r in [0, 1/3]
    float r2 = r * r;
    float q = fmaf(r2, 0.28571429f, 0.4f);
    q = fmaf(r2, q, 0.66666667f);
    q = fmaf(r2, q, 2.f);
    return fmaxf(s, 0.f) + r * q;
}

// ---- packed f32x2 helpers ---------------------------------------------------
__device__ __forceinline__ void ffma2(ull& d, ull a, ull b) {
    asm("fma.rn.f32x2 %0, %1, %2, %0;" : "+l"(d) : "l"(a), "l"(b));
}
__device__ __forceinline__ void add2(ull& d, ull o) {
    asm("add.rn.f32x2 %0, %0, %1;" : "+l"(d) : "l"(o));
}
__device__ __forceinline__ ull pack2(float lo, float hi) {
    ull r; asm("mov.b64 %0, {%1, %2};" : "=l"(r) : "f"(lo), "f"(hi)); return r;
}
__device__ __forceinline__ void unpack2(ull v, float& lo, float& hi) {
    asm("mov.b64 {%0, %1}, %2;" : "=f"(lo), "=f"(hi) : "l"(v));
}

// ------------------------- 256x256 fp32 GEMM (A powers) ---------------------
__global__ void mm256_kernel(const float* __restrict__ A,
                             const float* __restrict__ Bm,
                             float* __restrict__ C) {
    __shared__ float As[16][16];
    __shared__ float Bs[16][17];
    int tx = threadIdx.x, ty = threadIdx.y;
    int row = blockIdx.y * 16 + ty;
    int col = blockIdx.x * 16 + tx;
    float acc = 0.f;
    for (int k0 = 0; k0 < Sd; k0 += 16) {
        As[ty][tx] = A[(size_t)row * Sd + k0 + tx];
        Bs[ty][tx] = Bm[(size_t)(k0 + ty) * Sd + col];
        __syncthreads();
#pragma unroll
        for (int kk = 0; kk < 16; ++kk) acc += As[ty][kk] * Bs[kk][tx];
        __syncthreads();
    }
    C[(size_t)row * Sd + col] = acc;
}

// seeds[p] = (A^16)^p c — coalesced warp-per-row matvecs
__global__ void __launch_bounds__(256) seeds_kernel(const float* __restrict__ A16,
                                                    const float* __restrict__ Cssm) {
    __shared__ float w[Sd], nw[Sd];
    const int t = threadIdx.x, warp = t >> 5, lane = t & 31;
    w[t] = Cssm[t];
    g_seeds[t] = w[t];
    __syncthreads();
    for (int p = 1; p < 8; ++p) {
        const float4* wv = (const float4*)w;
        float4 v0 = wv[2 * lane], v1 = wv[2 * lane + 1];
#pragma unroll 4
        for (int rr = 0; rr < 32; ++rr) {
            int i = warp * 32 + rr;
            const float4* ar = (const float4*)(A16 + (size_t)i * Sd);
            float4 a0 = ar[2 * lane], a1 = ar[2 * lane + 1];
            float acc = a0.x * v0.x + a0.y * v0.y + a0.z * v0.z + a0.w * v0.w
                      + a1.x * v1.x + a1.y * v1.y + a1.z * v1.z + a1.w * v1.w;
#pragma unroll
            for (int o = 16; o > 0; o >>= 1) acc += __shfl_down_sync(0xffffffffu, acc, o);
            if (lane == 0) nw[i] = acc;
        }
        __syncthreads();
        w[t] = nw[t];
        g_seeds[p * Sd + t] = w[t];
        __syncthreads();
    }
}

// 8 parallel chains of 16 steps — coalesced warp-per-row
__global__ void __launch_bounds__(256) chains_kernel(const float* __restrict__ A,
                                                     const float* __restrict__ Bssm) {
    __shared__ float d[Sd], nd[Sd];
    const int t = threadIdx.x, warp = t >> 5, lane = t & 31;
    const int p = blockIdx.x;
    d[t] = g_seeds[p * Sd + t];
    __syncthreads();
    for (int k = 0; k < 16; ++k) {
        const float4* dv = (const float4*)d;
        float4 v0 = dv[2 * lane], v1 = dv[2 * lane + 1];
        // B projection: each warp handles 8 of the 64 M-rows
#pragma unroll
        for (int rr = 0; rr < 8; ++rr) {
            int m = warp * 8 + rr;
            const float4* br = (const float4*)(Bssm + (size_t)m * Sd);
            float4 b0 = br[2 * lane], b1 = br[2 * lane + 1];
            float acc = b0.x * v0.x + b0.y * v0.y + b0.z * v0.z + b0.w * v0.w
                      + b1.x * v1.x + b1.y * v1.y + b1.z * v1.z + b1.w * v1.w;
#pragma unroll
            for (int o = 16; o > 0; o >>= 1) acc += __shfl_down_sync(0xffffffffu, acc, o);
            if (lane == 0) g_M[(127 - (16 * p + k)) * MINd + m] = acc;
        }
        // A matvec: each warp handles 32 of the 256 rows
#pragma unroll 4
        for (int rr = 0; rr < 32; ++rr) {
            int i = warp * 32 + rr;
            const float4* ar = (const float4*)(A + (size_t)i * Sd);
            float4 a0 = ar[2 * lane], a1 = ar[2 * lane + 1];
            float acc = a0.x * v0.x + a0.y * v0.y + a0.z * v0.z + a0.w * v0.w
                      + a1.x * v1.x + a1.y * v1.y + a1.z * v1.z + a1.w * v1.w;
#pragma unroll
            for (int o = 16; o > 0; o >>= 1) acc += __shfl_down_sync(0xffffffffu, acc, o);
            if (lane == 0) nd[i] = acc;
        }
        __syncthreads();
        d[t] = nd[t];
        __syncthreads();
    }
}

// out[b] = wm * <x_mamba[b], M>   (537 MB stream; DRAM bound)
__global__ void __launch_bounds__(512) mamba_reduce_kernel(const float* __restrict__ xm,
                                                           const float* __restrict__ wm,
                                                           float* __restrict__ out) {
    __shared__ float4 Ms[2048];
    int t = threadIdx.x;
    const float4* Mg = (const float4*)g_M;
    for (int q = t; q < 2048; q += 512) Ms[q] = Mg[q];
    __syncthreads();
    int warp = t >> 5, lane = t & 31;
    int b = blockIdx.x * 16 + warp;
    const float4* xr = (const float4*)(xm + (size_t)b * (Td * MINd));
    float acc = 0.f;
#pragma unroll 8
    for (int j = lane; j < 2048; j += 32) {
        float4 xv = xr[j];
        float4 mv = Ms[j];
        acc += xv.x * mv.x + xv.y * mv.y + xv.z * mv.z + xv.w * mv.w;
    }
#pragma unroll
    for (int o = 16; o > 0; o >>= 1) acc += __shfl_down_sync(0xffffffffu, acc, o);
    if (lane == 0) out[b] = wm[0] * acc;
}

// row-sums of in_wb (over i) and in_bb (bias-collapse)
__global__ void ksums_kernel(const float* __restrict__ wb,
                             const float* __restrict__ bb) {
    int r = blockIdx.x, lane = threadIdx.x;
    float s = 0.f;
    if (r < 128) {
        const float* row = wb + (size_t)r * KINd;
        for (int i = lane; i < KINd; i += 32) s += row[i];
    } else if (r < 130) {
        const float* row = bb + (size_t)(r - 128) * KINd;
        for (int i = lane; i < KINd; i += 32) s += row[i];
    }
#pragma unroll
    for (int o = 16; o > 0; o >>= 1) s += __shfl_down_sync(0xffffffffu, s, o);
    if (lane == 0) {
        if (r < 128) g_sWb[r] = s;
        else if (r < 130) g_sbb[r - 128] = s;
    }
}

// h1 = relu(x @ W1[u] + b1[u]) — 128x128 block tile, f32x2 packed math
__global__ void __launch_bounds__(256) gemm1_kernel(const float* __restrict__ x,
                                                    const float* __restrict__ w1,
                                                    const float* __restrict__ b1) {
    __shared__ float xs[128][36];
    __shared__ float ws[32][128];
    const int u = blockIdx.x;
    const int b0 = blockIdx.y * 128;
    const int t = threadIdx.x;
    const int tx = t & 15;
    const int ty = t >> 4;
    const float* w1u = w1 + (size_t)u * KINd * H1d;
    const float* b1u = b1 + (size_t)u * H1d;

    ull acc2[8][4];
#pragma unroll
    for (int r = 0; r < 8; ++r)
#pragma unroll
        for (int j = 0; j < 4; ++j) acc2[r][j] = 0ULL;

    for (int k0 = 0; k0 < KINd; k0 += 32) {
        for (int q = t; q < 1024; q += 256) {
            int r = q >> 3, c = q & 7;
            *(float4*)&xs[r][c * 4] =
                *(const float4*)(x + (size_t)(b0 + r) * KINd + k0 + c * 4);
        }
        for (int q = t; q < 1024; q += 256) {
            int r = q >> 5, c = q & 31;
            *(float4*)&ws[r][c * 4] =
                *(const float4*)(w1u + (size_t)(k0 + r) * H1d + c * 4);
        }
        __syncthreads();
#pragma unroll 4
        for (int kk = 0; kk < 32; ++kk) {
            ull ap[8];
#pragma unroll
            for (int r = 0; r < 8; ++r) {
                float a = xs[ty * 8 + r][kk];
                ap[r] = pack2(a, a);
            }
            ulonglong2 wa = *(const ulonglong2*)&ws[kk][tx * 8];
            ulonglong2 wb = *(const ulonglong2*)&ws[kk][tx * 8 + 4];
#pragma unroll
            for (int r = 0; r < 8; ++r) {
                ffma2(acc2[r][0], ap[r], wa.x);
                ffma2(acc2[r][1], ap[r], wa.y);
                ffma2(acc2[r][2], ap[r], wb.x);
                ffma2(acc2[r][3], ap[r], wb.y);
            }
        }
        __syncthreads();
    }
#pragma unroll
    for (int r = 0; r < 8; ++r) {
        int b = b0 + ty * 8 + r;
        float* dst = g_h1 + ((size_t)b * 2 + u) * H1d + tx * 8;
#pragma unroll
        for (int j = 0; j < 4; ++j) {
            float lo, hi;
            unpack2(acc2[r][j], lo, hi);
            int n = tx * 8 + 2 * j;
            float v0 = fmaxf(lo + b1u[n], 0.f);
            float v1 = fmaxf(hi + b1u[n + 1], 0.f);
            float2 o2; o2.x = v0; o2.y = v1;
            *(float2*)(dst + 2 * j) = o2;
        }
    }
}

// h2 = relu(h1 @ W2[u] + b2[u])
__global__ void __launch_bounds__(256) gemm2_kernel(const float* __restrict__ w2,
                                                    const float* __restrict__ b2) {
    __shared__ float hs[64][65];
    __shared__ float w2s[64][64];
    const int u = blockIdx.x;
    const int b0 = blockIdx.y * 64;
    const int t = threadIdx.x;
    const int tx = t & 15;
    const int ty = t >> 4;
    const float* w2u = w2 + (size_t)u * H1d * H2d;

    float acc[4][4];
#pragma unroll
    for (int i = 0; i < 4; ++i)
#pragma unroll
        for (int j = 0; j < 4; ++j) acc[i][j] = 0.f;

    for (int k0 = 0; k0 < H1d; k0 += 64) {
        for (int q = t; q < 1024; q += 256) {
            int r = q >> 4, c = q & 15;
            float4 v = *(const float4*)(g_h1 + ((size_t)(b0 + r) * 2 + u) * H1d + k0 + c * 4);
            hs[r][c * 4 + 0] = v.x; hs[r][c * 4 + 1] = v.y;
            hs[r][c * 4 + 2] = v.z; hs[r][c * 4 + 3] = v.w;
        }
        for (int q = t; q < 1024; q += 256) {
            int r = q >> 4, c = q & 15;
            *(float4*)&w2s[r][c * 4] = *(const float4*)(w2u + (size_t)(k0 + r) * H2d + c * 4);
        }
        __syncthreads();
#pragma unroll 8
        for (int f = 0; f < 64; ++f) {
            float4 w = *(float4*)&w2s[f][tx * 4];
            float a0 = hs[ty * 4 + 0][f];
            float a1 = hs[ty * 4 + 1][f];
            float a2 = hs[ty * 4 + 2][f];
            float a3 = hs[ty * 4 + 3][f];
            acc[0][0] += a0 * w.x; acc[0][1] += a0 * w.y; acc[0][2] += a0 * w.z; acc[0][3] += a0 * w.w;
            acc[1][0] += a1 * w.x; acc[1][1] += a1 * w.y; acc[1][2] += a1 * w.z; acc[1][3] += a1 * w.w;
            acc[2][0] += a2 * w.x; acc[2][1] += a2 * w.y; acc[2][2] += a2 * w.z; acc[2][3] += a2 * w.w;
            acc[3][0] += a3 * w.x; acc[3][1] += a3 * w.y; acc[3][2] += a3 * w.z; acc[3][3] += a3 * w.w;
        }
        __syncthreads();
    }
#pragma unroll
    for (int i = 0; i < 4; ++i) {
        int b = b0 + ty * 4 + i;
#pragma unroll
        for (int j = 0; j < 4; ++j) {
            int g = tx * 4 + j;
            float v = acc[i][j] + b2[u * H2d + g];
            g_h2[((size_t)b * 2 + u) * H2d + g] = fmaxf(v, 0.f);
        }
    }
}

// inner[b,u] = sum_i softplus(h2.Ww[:,i]+bw[i])*x[b,i] + h2.sWb + sbb
__global__ void __launch_bounds__(256) stage2_kernel(const float* __restrict__ x,
                                                     const float* __restrict__ ww,
                                                     const float* __restrict__ bw) {
    extern __shared__ char sm[];
    float* h2tf = (float*)sm;              // [64][132]
    float* wws  = h2tf + 64 * 132;         // [64][68]
    float* xsh  = wws + 64 * 68;           // [128][68]
    float* bws  = xsh + 128 * 68;          // [64]
    float* sWbs = bws + 64;                // [64]
    const int u = blockIdx.x;
    const int b0 = blockIdx.y * 128;
    const int t = threadIdx.x;
    const int tx = t & 15;
    const int ty = t >> 4;
    const float* wwu = ww + (size_t)u * H2d * KINd;
    const float* bwu = bw + (size_t)u * KINd;

    if (t < 64) sWbs[t] = g_sWb[u * H2d + t];
    for (int q = t; q < 2048; q += 256) {
        int r = q & 127, gq = (q >> 7) * 4;
        float4 v = *(const float4*)(g_h2 + ((size_t)(b0 + r) * 2 + u) * H2d + gq);
        h2tf[(gq + 0) * 132 + r] = v.x;
        h2tf[(gq + 1) * 132 + r] = v.y;
        h2tf[(gq + 2) * 132 + r] = v.z;
        h2tf[(gq + 3) * 132 + r] = v.w;
    }
    __syncthreads();

    ull acc2[4][4];
    float part[8];
#pragma unroll
    for (int r = 0; r < 8; ++r) part[r] = 0.f;

    for (int it = 0; it < 16; ++it) {
        int i0 = it * 64;
        __syncthreads();
        for (int q = t; q < 1024; q += 256) {
            int r = q >> 4, c = q & 15;
            *(float4*)&wws[r * 68 + c * 4] =
                *(const float4*)(wwu + (size_t)r * KINd + i0 + c * 4);
        }
        for (int q = t; q < 2048; q += 256) {
            int r = q >> 4, c = q & 15;
            *(float4*)&xsh[r * 68 + c * 4] =
                *(const float4*)(x + (size_t)(b0 + r) * KINd + i0 + c * 4);
        }
        if (t < 16) *(float4*)&bws[t * 4] = *(const float4*)(bwu + i0 + t * 4);
        __syncthreads();

#pragma unroll
        for (int rp = 0; rp < 4; ++rp)
#pragma unroll
            for (int j = 0; j < 4; ++j) acc2[rp][j] = 0ULL;

#pragma unroll 4
        for (int g = 0; g < 64; ++g) {
            ulonglong2 ha = *(const ulonglong2*)(h2tf + g * 132 + ty * 8);
            ulonglong2 hb = *(const ulonglong2*)(h2tf + g * 132 + ty * 8 + 4);
            float4 wv = *(const float4*)&wws[g * 68 + tx * 4];
            ull w0 = pack2(wv.x, wv.x), w1p = pack2(wv.y, wv.y);
            ull w2p = pack2(wv.z, wv.z), w3p = pack2(wv.w, wv.w);
            ffma2(acc2[0][0], ha.x, w0); ffma2(acc2[0][1], ha.x, w1p);
            ffma2(acc2[0][2], ha.x, w2p); ffma2(acc2[0][3], ha.x, w3p);
            ffma2(acc2[1][0], ha.y, w0); ffma2(acc2[1][1], ha.y, w1p);
            ffma2(acc2[1][2], ha.y, w2p); ffma2(acc2[1][3], ha.y, w3p);
            ffma2(acc2[2][0], hb.x, w0); ffma2(acc2[2][1], hb.x, w1p);
            ffma2(acc2[2][2], hb.x, w2p); ffma2(acc2[2][3], hb.x, w3p);
            ffma2(acc2[3][0], hb.y, w0); ffma2(acc2[3][1], hb.y, w1p);
            ffma2(acc2[3][2], hb.y, w2p); ffma2(acc2[3][3], hb.y, w3p);
        }

#pragma unroll
        for (int j = 0; j < 4; ++j) {
            float bwv = bws[tx * 4 + j];
#pragma unroll
            for (int rp = 0; rp < 4; ++rp) {
                float s0, s1;
                unpack2(acc2[rp][j], s0, s1);
                float p0 = sp_poly(s0 + bwv);
                float p1 = sp_poly(s1 + bwv);
                part[2 * rp]     += p0 * xsh[(ty * 8 + 2 * rp) * 68 + tx * 4 + j];
                part[2 * rp + 1] += p1 * xsh[(ty * 8 + 2 * rp + 1) * 68 + tx * 4 + j];
            }
        }
    }

#pragma unroll
    for (int gg = 0; gg < 4; ++gg) {
        int g = tx * 4 + gg;
        float swv = sWbs[g];
#pragma unroll
        for (int r = 0; r < 8; ++r)
            part[r] += h2tf[g * 132 + ty * 8 + r] * swv;
    }
#pragma unroll
    for (int r = 0; r < 8; ++r)
#pragma unroll
        for (int o = 8; o > 0; o >>= 1)
            part[r] += __shfl_down_sync(0xffffffffu, part[r], o, 16);
    if (tx == 0) {
        float sbbv = g_sbb[u];
#pragma unroll
        for (int r = 0; r < 8; ++r)
            g_inner[(size_t)(b0 + ty * 8 + r) * 2 + u] = part[r] + sbbv;
    }
}

// outer MLP: out[b] += wk * kan_out[b]; thread = (b, v, f-half)
__global__ void __launch_bounds__(512) outer_kernel(const float* __restrict__ ow1,
                                                    const float* __restrict__ ob1,
                                                    const float* __restrict__ ow2,
                                                    const float* __restrict__ ob2,
                                                    const float* __restrict__ oww,
                                                    const float* __restrict__ obw,
                                                    const float* __restrict__ owb,
                                                    const float* __restrict__ obb,
                                                    const float* __restrict__ wk,
                                                    float* __restrict__ out) {
    extern __shared__ char sm[];
    float* OW2f = (float*)sm;   // [2][128][68]
    __shared__ float w1as[2][128], w1bs[2][128], b1s[2][128];
    __shared__ float ob2s[2][64], owws[2][64], owbs[2][64];
    const int t = threadIdx.x;
    const int bl = t >> 2;
    const int v = (t >> 1) & 1;
    const int hf = t & 1;
    const int b = blockIdx.x * 128 + bl;

    for (int q = t; q < 4096; q += 512) {
        int vv = q >> 11, f = (q >> 4) & 127, c = q & 15;
        *(float4*)&OW2f[(vv * 128 + f) * 68 + c * 4] =
            *(const float4*)(ow2 + ((size_t)vv * 128 + f) * 64 + c * 4);
    }
    if (t < 256) {
        int vv = t >> 7, f = t & 127;
        w1as[vv][f] = ow1[(vv * 2 + 0) * 128 + f];
        w1bs[vv][f] = ow1[(vv * 2 + 1) * 128 + f];
        b1s[vv][f]  = ob1[vv * 128 + f];
    }
    if (t < 128) {
        int vv = t >> 6, j = t & 63;
        ob2s[vv][j] = ob2[vv * 64 + j];
        owws[vv][j] = oww[vv * 64 + j];
        owbs[vv][j] = owb[vv * 64 + j];
    }
    __syncthreads();

    const float i0 = g_inner[(size_t)b * 2 + 0];
    const float i1 = g_inner[(size_t)b * 2 + 1];

    ull g2a[32];
#pragma unroll
    for (int j = 0; j < 32; ++j)
        g2a[j] = (hf == 0) ? pack2(ob2s[v][2 * j], ob2s[v][2 * j + 1]) : 0ULL;

    const float* OW2v = OW2f + v * 128 * 68;
#pragma unroll 2
    for (int ff = 0; ff < 64; ++ff) {
        int f = hf * 64 + ff;
        float g1f = fmaxf(fmaf(i0, w1as[v][f], fmaf(i1, w1bs[v][f], b1s[v][f])), 0.f);
        ull g1p = pack2(g1f, g1f);
        const ull* row = (const ull*)(OW2v + f * 68);
#pragma unroll
        for (int j = 0; j < 32; ++j) ffma2(g2a[j], g1p, row[j]);
    }
#pragma unroll
    for (int j = 0; j < 32; ++j) {
        ull o = __shfl_xor_sync(0xffffffffu, g2a[j], 1);
        add2(g2a[j], o);
    }
    float sw = 0.f, sb = 0.f;
#pragma unroll
    for (int j = 0; j < 32; ++j) {
        float a, c2;
        unpack2(g2a[j], a, c2);
        a = fmaxf(a, 0.f); c2 = fmaxf(c2, 0.f);
        sw += a * owws[v][2 * j] + c2 * owws[v][2 * j + 1];
        sb += a * owbs[v][2 * j] + c2 * owbs[v][2 * j + 1];
    }
    float wout = sp_poly(sw + obw[v]);
    float bout = sb + obb[v];
    float term = wout * (i0 + i1) + 2.f * bout;
    term += __shfl_xor_sync(0xffffffffu, term, 2);
    if ((t & 3) == 0) out[b] += wk[0] * term;
}

extern "C" void kernel_launch(void* const* d_in, const int* in_sizes, int n_in,
                              void* d_out, int out_size) {
    const float* x_kan   = (const float*)d_in[0];
    const float* x_mamba = (const float*)d_in[1];
    const float* in_w1 = (const float*)d_in[2];
    const float* in_b1 = (const float*)d_in[3];
    const float* in_w2 = (const float*)d_in[4];
    const float* in_b2 = (const float*)d_in[5];
    const float* in_ww = (const float*)d_in[6];
    const float* in_bw = (const float*)d_in[7];
    const float* in_wb = (const float*)d_in[8];
    const float* in_bb = (const float*)d_in[9];
    const float* out_w1 = (const float*)d_in[10];
    const float* out_b1 = (const float*)d_in[11];
    const float* out_w2 = (const float*)d_in[12];
    const float* out_b2 = (const float*)d_in[13];
    const float* out_ww = (const float*)d_in[14];
    const float* out_bw = (const float*)d_in[15];
    const float* out_wb = (const float*)d_in[16];
    const float* out_bb = (const float*)d_in[17];
    const float* A      = (const float*)d_in[18];
    const float* B_ssm  = (const float*)d_in[19];
    const float* C_ssm  = (const float*)d_in[20];
    const float* wk     = (const float*)d_in[21];
    const float* wm     = (const float*)d_in[22];
    float* out = (float*)d_out;

    float *gP, *gQ;
    cudaGetSymbolAddress((void**)&gP, g_P);
    cudaGetSymbolAddress((void**)&gQ, g_Q);

    const int S2SMEM = (64 * 132 + 64 * 68 + 128 * 68 + 64 + 64) * 4;   // 86528
    const int OSMEM  = 2 * 128 * 68 * 4;                                 // 69632
    cudaFuncSetAttribute(stage2_kernel, cudaFuncAttributeMaxDynamicSharedMemorySize, S2SMEM);
    cudaFuncSetAttribute(outer_kernel, cudaFuncAttributeMaxDynamicSharedMemorySize, OSMEM);

    dim3 b16(16, 16), g16(16, 16);
    ksums_kernel<<<130, 32>>>(in_wb, in_bb);                        // 1
    gemm1_kernel<<<dim3(2, Bn / 128), 256>>>(x_kan, in_w1, in_b1);  // 2
    gemm2_kernel<<<dim3(2, Bn / 64), 256>>>(in_w2, in_b2);          // 3
    mm256_kernel<<<g16, b16>>>(A, A, gP);                           // 4 (A^2)
    stage2_kernel<<<dim3(2, Bn / 128), 256, S2SMEM>>>(x_kan, in_ww, in_bw); // 5 (profile target)
    mm256_kernel<<<g16, b16>>>(gP, gP, gQ);                         // 6 (A^4)
    mm256_kernel<<<g16, b16>>>(gQ, gQ, gP);                         // 7 (A^8)
    mm256_kernel<<<g16, b16>>>(gP, gP, gQ);                         // 8 (A^16)
    seeds_kernel<<<1, 256>>>(gQ, C_ssm);                            // 9
    chains_kernel<<<8, 256>>>(A, B_ssm);                            // 10
    mamba_reduce_kernel<<<Bn / 16, 512>>>(x_mamba, wm, out);        // 11
    outer_kernel<<<Bn / 128, 512, OSMEM>>>(out_w1, out_b1, out_w2, out_b2,
                                           out_ww, out_bw, out_wb, out_bb, wk, out); // 12
}

// round 7
// speedup vs baseline: 2.2632x; 1.0891x over previous
#include <cuda_runtime.h>
#include <math.h>
#include <cstdint>

#define Bn    16384
#define KINd  1024
#define MINd  64
#define Sd    256
#define Td    128
#define H1d   128
#define H2d   64

typedef unsigned long long ull;

// ------------------------- scratch (device globals; no allocs) --------------
static __device__ __align__(16) float g_P1[Sd * Sd];
static __device__ __align__(16) float g_P2[Sd * Sd];
static __device__ __align__(16) float g_P3[Sd * Sd];
static __device__ __align__(16) float g_Q[Sd * Sd];     // A^16
static __device__ __align__(16) float g_seeds[8 * Sd];
static __device__ __align__(16) float g_CS[8 * Sd];     // chains mid-state
static __device__ __align__(16) float g_M[Td * MINd];
static __device__ __align__(16) float g_h1[(size_t)Bn * 2 * H1d];   // 16 MB
static __device__ __align__(16) float g_h2[(size_t)Bn * 2 * H2d];   // 8 MB
static __device__ __align__(16) float g_inner[(size_t)Bn * 2];
static __device__ float g_sWb[2 * H2d];
static __device__ float g_sbb[2];
static __device__ volatile int g_sync[8];

// ---- FMA-only softplus (no MUFU) -------------------------------------------
__device__ __forceinline__ float sp_poly(float s) {
    float t = fmaxf(-fabsf(s), -17.f);
    float z = t * 1.44269504f;
    int   ni = __float2int_rn(z);
    float f = z - (float)ni;
    float p = 1.33335581e-3f;
    p = fmaf(p, f, 9.61812911e-3f);
    p = fmaf(p, f, 5.55041087e-2f);
    p = fmaf(p, f, 2.40226507e-1f);
    p = fmaf(p, f, 6.93147181e-1f);
    p = fmaf(p, f, 1.f);
    float y = __int_as_float((ni + 127) << 23) * p;
    float v = 2.f + y;
    float r0 = fmaf(-0.1716f, v, 0.8249f);
    r0 = r0 * fmaf(-v, r0, 2.f);
    r0 = r0 * fmaf(-v, r0, 2.f);
    float r  = y * r0;
    float r2 = r * r;
    float q = fmaf(r2, 0.28571429f, 0.4f);
    q = fmaf(r2, q, 0.66666667f);
    q = fmaf(r2, q, 2.f);
    return fmaxf(s, 0.f) + r * q;
}

// ---- packed f32x2 helpers ---------------------------------------------------
__device__ __forceinline__ void ffma2(ull& d, ull a, ull b) {
    asm("fma.rn.f32x2 %0, %1, %2, %0;" : "+l"(d) : "l"(a), "l"(b));
}
__device__ __forceinline__ void add2(ull& d, ull o) {
    asm("add.rn.f32x2 %0, %0, %1;" : "+l"(d) : "l"(o));
}
__device__ __forceinline__ ull pack2(float lo, float hi) {
    ull r; asm("mov.b64 %0, {%1, %2};" : "=l"(r) : "f"(lo), "f"(hi)); return r;
}
__device__ __forceinline__ void unpack2(ull v, float& lo, float& hi) {
    asm("mov.b64 {%0, %1}, %2;" : "=f"(lo), "=f"(hi) : "l"(v));
}

// ---- resident-grid sync (64 blocks; counters reset by ksums each replay) ---
__device__ __forceinline__ void grid_sync(int s, int n) {
    __threadfence();
    __syncthreads();
    if (threadIdx.x == 0) {
        atomicAdd((int*)&g_sync[s], 1);
        while (*(volatile int*)&g_sync[s] < n) { }
        __threadfence();
    }
    __syncthreads();
}

// ------------------------- A^16 in one kernel (4 GEMM stages) ----------------
__global__ void __launch_bounds__(256) apow_kernel(const float* __restrict__ A) {
    extern __shared__ char dynsm[];
    float* As = (float*)dynsm;            // [256][34] transposed L tile
    float* Bs = (float*)dynsm + 256 * 34; // [256][36] R tile
    const int t = threadIdx.x, tx = t & 15, ty = t >> 4;
    const int rb = (blockIdx.x >> 3) * 32, cb = (blockIdx.x & 7) * 32;

#pragma unroll
    for (int s = 0; s < 4; ++s) {
        const float* L = (s == 0) ? A : (s == 1) ? g_P1 : (s == 2) ? g_P2 : g_P3;
        float* C = (s == 0) ? g_P1 : (s == 1) ? g_P2 : (s == 2) ? g_P3 : g_Q;
        for (int q = t; q < 2048; q += 256) {
            int i = q >> 6, k4 = (q & 63) * 4;
            float4 v = *(const float4*)(L + (size_t)(rb + i) * Sd + k4);
            As[(k4 + 0) * 34 + i] = v.x;
            As[(k4 + 1) * 34 + i] = v.y;
            As[(k4 + 2) * 34 + i] = v.z;
            As[(k4 + 3) * 34 + i] = v.w;
        }
        for (int q = t; q < 2048; q += 256) {
            int k = q >> 3, j4 = (q & 7) * 4;
            *(float4*)&Bs[k * 36 + j4] = *(const float4*)(L + (size_t)k * Sd + cb + j4);
        }
        __syncthreads();
        float c00 = 0.f, c01 = 0.f, c10 = 0.f, c11 = 0.f;
#pragma unroll 8
        for (int k = 0; k < 256; ++k) {
            float2 av = *(float2*)&As[k * 34 + ty * 2];
            float2 bv = *(float2*)&Bs[k * 36 + tx * 2];
            c00 += av.x * bv.x; c01 += av.x * bv.y;
            c10 += av.y * bv.x; c11 += av.y * bv.y;
        }
        C[(size_t)(rb + ty * 2) * Sd + cb + tx * 2]         = c00;
        C[(size_t)(rb + ty * 2) * Sd + cb + tx * 2 + 1]     = c01;
        C[(size_t)(rb + ty * 2 + 1) * Sd + cb + tx * 2]     = c10;
        C[(size_t)(rb + ty * 2 + 1) * Sd + cb + tx * 2 + 1] = c11;
        if (s < 3) {
            grid_sync(s, 64);
            __syncthreads();
        }
    }
}

// seeds[p] = (A^16)^p c — coalesced warp-per-row matvecs
__global__ void __launch_bounds__(256) seeds_kernel(const float* __restrict__ Cssm) {
    __shared__ float w[Sd], nw[Sd];
    const int t = threadIdx.x, warp = t >> 5, lane = t & 31;
    w[t] = Cssm[t];
    g_seeds[t] = w[t];
    __syncthreads();
    for (int p = 1; p < 8; ++p) {
        const float4* wv = (const float4*)w;
        float4 v0 = wv[2 * lane], v1 = wv[2 * lane + 1];
#pragma unroll 4
        for (int rr = 0; rr < 32; ++rr) {
            int i = warp * 32 + rr;
            const float4* ar = (const float4*)(g_Q + (size_t)i * Sd);
            float4 a0 = ar[2 * lane], a1 = ar[2 * lane + 1];
            float acc = a0.x * v0.x + a0.y * v0.y + a0.z * v0.z + a0.w * v0.w
                      + a1.x * v1.x + a1.y * v1.y + a1.z * v1.z + a1.w * v1.w;
#pragma unroll
            for (int o = 16; o > 0; o >>= 1) acc += __shfl_down_sync(0xffffffffu, acc, o);
            if (lane == 0) nw[i] = acc;
        }
        __syncthreads();
        w[t] = nw[t];
        g_seeds[p * Sd + t] = w[t];
        __syncthreads();
    }
}

// 8 parallel chains, 8 steps per launch (split so profile slot lands right)
__global__ void __launch_bounds__(256) chains_kernel(const float* __restrict__ A,
                                                     const float* __restrict__ Bssm,
                                                     int kstart) {
    __shared__ float d[Sd], nd[Sd];
    const int t = threadIdx.x, warp = t >> 5, lane = t & 31;
    const int p = blockIdx.x;
    d[t] = (kstart == 0) ? g_seeds[p * Sd + t] : g_CS[p * Sd + t];
    __syncthreads();
    for (int kk = 0; kk < 8; ++kk) {
        const int k = kstart + kk;
        const float4* dv = (const float4*)d;
        float4 v0 = dv[2 * lane], v1 = dv[2 * lane + 1];
#pragma unroll
        for (int rr = 0; rr < 8; ++rr) {
            int m = warp * 8 + rr;
            const float4* br = (const float4*)(Bssm + (size_t)m * Sd);
            float4 b0 = br[2 * lane], b1 = br[2 * lane + 1];
            float acc = b0.x * v0.x + b0.y * v0.y + b0.z * v0.z + b0.w * v0.w
                      + b1.x * v1.x + b1.y * v1.y + b1.z * v1.z + b1.w * v1.w;
#pragma unroll
            for (int o = 16; o > 0; o >>= 1) acc += __shfl_down_sync(0xffffffffu, acc, o);
            if (lane == 0) g_M[(127 - (16 * p + k)) * MINd + m] = acc;
        }
#pragma unroll 4
        for (int rr = 0; rr < 32; ++rr) {
            int i = warp * 32 + rr;
            const float4* ar = (const float4*)(A + (size_t)i * Sd);
            float4 a0 = ar[2 * lane], a1 = ar[2 * lane + 1];
            float acc = a0.x * v0.x + a0.y * v0.y + a0.z * v0.z + a0.w * v0.w
                      + a1.x * v1.x + a1.y * v1.y + a1.z * v1.z + a1.w * v1.w;
#pragma unroll
            for (int o = 16; o > 0; o >>= 1) acc += __shfl_down_sync(0xffffffffu, acc, o);
            if (lane == 0) nd[i] = acc;
        }
        __syncthreads();
        d[t] = nd[t];
        __syncthreads();
    }
    g_CS[p * Sd + t] = d[t];
}

// row-sums of in_wb / in_bb (bias-collapse) + sync-counter reset for replays
__global__ void ksums_kernel(const float* __restrict__ wb,
                             const float* __restrict__ bb) {
    int r = blockIdx.x, lane = threadIdx.x;
    if (r == 0 && lane == 0) {
#pragma unroll
        for (int s = 0; s < 8; ++s) g_sync[s] = 0;
    }
    float s = 0.f;
    if (r < 128) {
        const float* row = wb + (size_t)r * KINd;
        for (int i = lane; i < KINd; i += 32) s += row[i];
    } else if (r < 130) {
        const float* row = bb + (size_t)(r - 128) * KINd;
        for (int i = lane; i < KINd; i += 32) s += row[i];
    }
#pragma unroll
    for (int o = 16; o > 0; o >>= 1) s += __shfl_down_sync(0xffffffffu, s, o);
    if (lane == 0) {
        if (r < 128) g_sWb[r] = s;
        else if (r < 130) g_sbb[r - 128] = s;
    }
}

// ---------- combined kernel: gemm1 (blocks 0..255) + mamba reduce (256..) ----
__global__ void __launch_bounds__(256) g1mamba_kernel(const float* __restrict__ x,
                                                      const float* __restrict__ w1,
                                                      const float* __restrict__ b1,
                                                      const float* __restrict__ xm,
                                                      const float* __restrict__ wm,
                                                      float* __restrict__ out) {
    extern __shared__ char dynsm[];
    const int bid = blockIdx.x;
    const int t = threadIdx.x;

    if (bid < 256) {
        // ---- gemm1 path ----
        float* xs = (float*)dynsm;               // [128][36]
        float* ws = (float*)dynsm + 128 * 36;    // [32][128]
        const int u = bid & 1;
        const int b0 = (bid >> 1) * 128;
        const int tx = t & 15;
        const int ty = t >> 4;
        const float* w1u = w1 + (size_t)u * KINd * H1d;
        const float* b1u = b1 + (size_t)u * H1d;

        ull acc2[8][4];
#pragma unroll
        for (int r = 0; r < 8; ++r)
#pragma unroll
            for (int j = 0; j < 4; ++j) acc2[r][j] = 0ULL;

        for (int k0 = 0; k0 < KINd; k0 += 32) {
            for (int q = t; q < 1024; q += 256) {
                int r = q >> 3, c = q & 7;
                *(float4*)&xs[r * 36 + c * 4] =
                    *(const float4*)(x + (size_t)(b0 + r) * KINd + k0 + c * 4);
            }
            for (int q = t; q < 1024; q += 256) {
                int r = q >> 5, c = q & 31;
                *(float4*)&ws[r * 128 + c * 4] =
                    *(const float4*)(w1u + (size_t)(k0 + r) * H1d + c * 4);
            }
            __syncthreads();
#pragma unroll 4
            for (int kk = 0; kk < 32; ++kk) {
                ull ap[8];
#pragma unroll
                for (int r = 0; r < 8; ++r) {
                    float a = xs[(ty * 8 + r) * 36 + kk];
                    ap[r] = pack2(a, a);
                }
                ulonglong2 wa = *(const ulonglong2*)&ws[kk * 128 + tx * 8];
                ulonglong2 wb = *(const ulonglong2*)&ws[kk * 128 + tx * 8 + 4];
#pragma unroll
                for (int r = 0; r < 8; ++r) {
                    ffma2(acc2[r][0], ap[r], wa.x);
                    ffma2(acc2[r][1], ap[r], wa.y);
                    ffma2(acc2[r][2], ap[r], wb.x);
                    ffma2(acc2[r][3], ap[r], wb.y);
                }
            }
            __syncthreads();
        }
#pragma unroll
        for (int r = 0; r < 8; ++r) {
            int b = b0 + ty * 8 + r;
            float* dst = g_h1 + ((size_t)b * 2 + u) * H1d + tx * 8;
#pragma unroll
            for (int j = 0; j < 4; ++j) {
                float lo, hi;
                unpack2(acc2[r][j], lo, hi);
                int n = tx * 8 + 2 * j;
                float v0 = fmaxf(lo + b1u[n], 0.f);
                float v1 = fmaxf(hi + b1u[n + 1], 0.f);
                float2 o2; o2.x = v0; o2.y = v1;
                *(float2*)(dst + 2 * j) = o2;
            }
        }
    } else {
        // ---- mamba path: 8 warps, one row each ----
        float4* Ms = (float4*)dynsm;     // 2048 float4 = 32 KB
        const float4* Mg = (const float4*)g_M;
        for (int q = t; q < 2048; q += 256) Ms[q] = Mg[q];
        __syncthreads();
        const int warp = t >> 5, lane = t & 31;
        const int b = (bid - 256) * 8 + warp;
        const float4* xr = (const float4*)(xm + (size_t)b * (Td * MINd));
        float acc = 0.f;
#pragma unroll 8
        for (int j = lane; j < 2048; j += 32) {
            float4 xv = xr[j];
            float4 mv = Ms[j];
            acc += xv.x * mv.x + xv.y * mv.y + xv.z * mv.z + xv.w * mv.w;
        }
#pragma unroll
        for (int o = 16; o > 0; o >>= 1) acc += __shfl_down_sync(0xffffffffu, acc, o);
        if (lane == 0) out[b] = wm[0] * acc;
    }
}

// h2 = relu(h1 @ W2[u] + b2[u])
__global__ void __launch_bounds__(256) gemm2_kernel(const float* __restrict__ w2,
                                                    const float* __restrict__ b2) {
    __shared__ float hs[64][65];
    __shared__ float w2s[64][64];
    const int u = blockIdx.x;
    const int b0 = blockIdx.y * 64;
    const int t = threadIdx.x;
    const int tx = t & 15;
    const int ty = t >> 4;
    const float* w2u = w2 + (size_t)u * H1d * H2d;

    float acc[4][4];
#pragma unroll
    for (int i = 0; i < 4; ++i)
#pragma unroll
        for (int j = 0; j < 4; ++j) acc[i][j] = 0.f;

    for (int k0 = 0; k0 < H1d; k0 += 64) {
        for (int q = t; q < 1024; q += 256) {
            int r = q >> 4, c = q & 15;
            float4 v = *(const float4*)(g_h1 + ((size_t)(b0 + r) * 2 + u) * H1d + k0 + c * 4);
            hs[r][c * 4 + 0] = v.x; hs[r][c * 4 + 1] = v.y;
            hs[r][c * 4 + 2] = v.z; hs[r][c * 4 + 3] = v.w;
        }
        for (int q = t; q < 1024; q += 256) {
            int r = q >> 4, c = q & 15;
            *(float4*)&w2s[r][c * 4] = *(const float4*)(w2u + (size_t)(k0 + r) * H2d + c * 4);
        }
        __syncthreads();
#pragma unroll 8
        for (int f = 0; f < 64; ++f) {
            float4 w = *(float4*)&w2s[f][tx * 4];
            float a0 = hs[ty * 4 + 0][f];
            float a1 = hs[ty * 4 + 1][f];
            float a2 = hs[ty * 4 + 2][f];
            float a3 = hs[ty * 4 + 3][f];
            acc[0][0] += a0 * w.x; acc[0][1] += a0 * w.y; acc[0][2] += a0 * w.z; acc[0][3] += a0 * w.w;
            acc[1][0] += a1 * w.x; acc[1][1] += a1 * w.y; acc[1][2] += a1 * w.z; acc[1][3] += a1 * w.w;
            acc[2][0] += a2 * w.x; acc[2][1] += a2 * w.y; acc[2][2] += a2 * w.z; acc[2][3] += a2 * w.w;
            acc[3][0] += a3 * w.x; acc[3][1] += a3 * w.y; acc[3][2] += a3 * w.z; acc[3][3] += a3 * w.w;
        }
        __syncthreads();
    }
#pragma unroll
    for (int i = 0; i < 4; ++i) {
        int b = b0 + ty * 4 + i;
#pragma unroll
        for (int j = 0; j < 4; ++j) {
            int g = tx * 4 + j;
            float v = acc[i][j] + b2[u * H2d + g];
            g_h2[((size_t)b * 2 + u) * H2d + g] = fmaxf(v, 0.f);
        }
    }
}

// inner[b,u] = sum_i softplus(h2.Ww[:,i]+bw[i])*x[b,i] + h2.sWb + sbb
__global__ void __launch_bounds__(256) stage2_kernel(const float* __restrict__ x,
                                                     const float* __restrict__ ww,
                                                     const float* __restrict__ bw) {
    extern __shared__ char dynsm[];
    float* h2tf = (float*)dynsm;           // [64][132]
    float* wws  = h2tf + 64 * 132;         // [64][68]
    float* xsh  = wws + 64 * 68;           // [128][68]
    float* bws  = xsh + 128 * 68;          // [64]
    float* sWbs = bws + 64;                // [64]
    const int u = blockIdx.x;
    const int b0 = blockIdx.y * 128;
    const int t = threadIdx.x;
    const int tx = t & 15;
    const int ty = t >> 4;
    const float* wwu = ww + (size_t)u * H2d * KINd;
    const float* bwu = bw + (size_t)u * KINd;

    if (t < 64) sWbs[t] = g_sWb[u * H2d + t];
    for (int q = t; q < 2048; q += 256) {
        int r = q & 127, gq = (q >> 7) * 4;
        float4 v = *(const float4*)(g_h2 + ((size_t)(b0 + r) * 2 + u) * H2d + gq);
        h2tf[(gq + 0) * 132 + r] = v.x;
        h2tf[(gq + 1) * 132 + r] = v.y;
        h2tf[(gq + 2) * 132 + r] = v.z;
        h2tf[(gq + 3) * 132 + r] = v.w;
    }
    __syncthreads();

    ull acc2[4][4];
    float part[8];
#pragma unroll
    for (int r = 0; r < 8; ++r) part[r] = 0.f;

    for (int it = 0; it < 16; ++it) {
        int i0 = it * 64;
        __syncthreads();
        for (int q = t; q < 1024; q += 256) {
            int r = q >> 4, c = q & 15;
            *(float4*)&wws[r * 68 + c * 4] =
                *(const float4*)(wwu + (size_t)r * KINd + i0 + c * 4);
        }
        for (int q = t; q < 2048; q += 256) {
            int r = q >> 4, c = q & 15;
            *(float4*)&xsh[r * 68 + c * 4] =
                *(const float4*)(x + (size_t)(b0 + r) * KINd + i0 + c * 4);
        }
        if (t < 16) *(float4*)&bws[t * 4] = *(const float4*)(bwu + i0 + t * 4);
        __syncthreads();

#pragma unroll
        for (int rp = 0; rp < 4; ++rp)
#pragma unroll
            for (int j = 0; j < 4; ++j) acc2[rp][j] = 0ULL;

#pragma unroll 4
        for (int g = 0; g < 64; ++g) {
            ulonglong2 ha = *(const ulonglong2*)(h2tf + g * 132 + ty * 8);
            ulonglong2 hb = *(const ulonglong2*)(h2tf + g * 132 + ty * 8 + 4);
            float4 wv = *(const float4*)&wws[g * 68 + tx * 4];
            ull w0 = pack2(wv.x, wv.x), w1p = pack2(wv.y, wv.y);
            ull w2p = pack2(wv.z, wv.z), w3p = pack2(wv.w, wv.w);
            ffma2(acc2[0][0], ha.x, w0); ffma2(acc2[0][1], ha.x, w1p);
            ffma2(acc2[0][2], ha.x, w2p); ffma2(acc2[0][3], ha.x, w3p);
            ffma2(acc2[1][0], ha.y, w0); ffma2(acc2[1][1], ha.y, w1p);
            ffma2(acc2[1][2], ha.y, w2p); ffma2(acc2[1][3], ha.y, w3p);
            ffma2(acc2[2][0], hb.x, w0); ffma2(acc2[2][1], hb.x, w1p);
            ffma2(acc2[2][2], hb.x, w2p); ffma2(acc2[2][3], hb.x, w3p);
            ffma2(acc2[3][0], hb.y, w0); ffma2(acc2[3][1], hb.y, w1p);
            ffma2(acc2[3][2], hb.y, w2p); ffma2(acc2[3][3], hb.y, w3p);
        }

#pragma unroll
        for (int j = 0; j < 4; ++j) {
            float bwv = bws[tx * 4 + j];
#pragma unroll
            for (int rp = 0; rp < 4; ++rp) {
                float s0, s1;
                unpack2(acc2[rp][j], s0, s1);
                float p0 = sp_poly(s0 + bwv);
                float p1 = sp_poly(s1 + bwv);
                part[2 * rp]     += p0 * xsh[(ty * 8 + 2 * rp) * 68 + tx * 4 + j];
                part[2 * rp + 1] += p1 * xsh[(ty * 8 + 2 * rp + 1) * 68 + tx * 4 + j];
            }
        }
    }

#pragma unroll
    for (int gg = 0; gg < 4; ++gg) {
        int g = tx * 4 + gg;
        float swv = sWbs[g];
#pragma unroll
        for (int r = 0; r < 8; ++r)
            part[r] += h2tf[g * 132 + ty * 8 + r] * swv;
    }
#pragma unroll
    for (int r = 0; r < 8; ++r)
#pragma unroll
        for (int o = 8; o > 0; o >>= 1)
            part[r] += __shfl_down_sync(0xffffffffu, part[r], o, 16);
    if (tx == 0) {
        float sbbv = g_sbb[u];
#pragma unroll
        for (int r = 0; r < 8; ++r)
            g_inner[(size_t)(b0 + ty * 8 + r) * 2 + u] = part[r] + sbbv;
    }
}

// outer MLP: out[b] += wk * kan_out[b]; thread = (b, v, f-half)
__global__ void __launch_bounds__(512) outer_kernel(const float* __restrict__ ow1,
                                                    const float* __restrict__ ob1,
                                                    const float* __restrict__ ow2,
                                                    const float* __restrict__ ob2,
                                                    const float* __restrict__ oww,
                                                    const float* __restrict__ obw,
                                                    const float* __restrict__ owb,
                                                    const float* __restrict__ obb,
                                                    const float* __restrict__ wk,
                                                    float* __restrict__ out) {
    extern __shared__ char dynsm[];
    float* OW2f = (float*)dynsm;   // [2][128][68]
    __shared__ float w1as[2][128], w1bs[2][128], b1s[2][128];
    __shared__ float ob2s[2][64], owws[2][64], owbs[2][64];
    const int t = threadIdx.x;
    const int bl = t >> 2;
    const int v = (t >> 1) & 1;
    const int hf = t & 1;
    const int b = blockIdx.x * 128 + bl;

    for (int q = t; q < 4096; q += 512) {
        int vv = q >> 11, f = (q >> 4) & 127, c = q & 15;
        *(float4*)&OW2f[(vv * 128 + f) * 68 + c * 4] =
            *(const float4*)(ow2 + ((size_t)vv * 128 + f) * 64 + c * 4);
    }
    if (t < 256) {
        int vv = t >> 7, f = t & 127;
        w1as[vv][f] = ow1[(vv * 2 + 0) * 128 + f];
        w1bs[vv][f] = ow1[(vv * 2 + 1) * 128 + f];
        b1s[vv][f]  = ob1[vv * 128 + f];
    }
    if (t < 128) {
        int vv = t >> 6, j = t & 63;
        ob2s[vv][j] = ob2[vv * 64 + j];
        owws[vv][j] = oww[vv * 64 + j];
        owbs[vv][j] = owb[vv * 64 + j];
    }
    __syncthreads();

    const float i0 = g_inner[(size_t)b * 2 + 0];
    const float i1 = g_inner[(size_t)b * 2 + 1];

    ull g2a[32];
#pragma unroll
    for (int j = 0; j < 32; ++j)
        g2a[j] = (hf == 0) ? pack2(ob2s[v][2 * j], ob2s[v][2 * j + 1]) : 0ULL;

    const float* OW2v = OW2f + v * 128 * 68;
#pragma unroll 2
    for (int ff = 0; ff < 64; ++ff) {
        int f = hf * 64 + ff;
        float g1f = fmaxf(fmaf(i0, w1as[v][f], fmaf(i1, w1bs[v][f], b1s[v][f])), 0.f);
        ull g1p = pack2(g1f, g1f);
        const ull* row = (const ull*)(OW2v + f * 68);
#pragma unroll
        for (int j = 0; j < 32; ++j) ffma2(g2a[j], g1p, row[j]);
    }
#pragma unroll
    for (int j = 0; j < 32; ++j) {
        ull o = __shfl_xor_sync(0xffffffffu, g2a[j], 1);
        add2(g2a[j], o);
    }
    float sw = 0.f, sb = 0.f;
#pragma unroll
    for (int j = 0; j < 32; ++j) {
        float a, c2;
        unpack2(g2a[j], a, c2);
        a = fmaxf(a, 0.f); c2 = fmaxf(c2, 0.f);
        sw += a * owws[v][2 * j] + c2 * owws[v][2 * j + 1];
        sb += a * owbs[v][2 * j] + c2 * owbs[v][2 * j + 1];
    }
    float wout = sp_poly(sw + obw[v]);
    float bout = sb + obb[v];
    float term = wout * (i0 + i1) + 2.f * bout;
    term += __shfl_xor_sync(0xffffffffu, term, 2);
    if ((t & 3) == 0) out[b] += wk[0] * term;
}

extern "C" void kernel_launch(void* const* d_in, const int* in_sizes, int n_in,
                              void* d_out, int out_size) {
    const float* x_kan   = (const float*)d_in[0];
    const float* x_mamba = (const float*)d_in[1];
    const float* in_w1 = (const float*)d_in[2];
    const float* in_b1 = (const float*)d_in[3];
    const float* in_w2 = (const float*)d_in[4];
    const float* in_b2 = (const float*)d_in[5];
    const float* in_ww = (const float*)d_in[6];
    const float* in_bw = (const float*)d_in[7];
    const float* in_wb = (const float*)d_in[8];
    const float* in_bb = (const float*)d_in[9];
    const float* out_w1 = (const float*)d_in[10];
    const float* out_b1 = (const float*)d_in[11];
    const float* out_w2 = (const float*)d_in[12];
    const float* out_b2 = (const float*)d_in[13];
    const float* out_ww = (const float*)d_in[14];
    const float* out_bw = (const float*)d_in[15];
    const float* out_wb = (const float*)d_in[16];
    const float* out_bb = (const float*)d_in[17];
    const float* A      = (const float*)d_in[18];
    const float* B_ssm  = (const float*)d_in[19];
    const float* C_ssm  = (const float*)d_in[20];
    const float* wk     = (const float*)d_in[21];
    const float* wm     = (const float*)d_in[22];
    float* out = (float*)d_out;

    const int APSMEM = (256 * 34 + 256 * 36) * 4;                        // 71680
    const int G1SMEM = (128 * 36 + 32 * 128) * 4;                        // 34816
    const int S2SMEM = (64 * 132 + 64 * 68 + 128 * 68 + 64 + 64) * 4;    // 86528
    const int OSMEM  = 2 * 128 * 68 * 4;                                  // 69632
    cudaFuncSetAttribute(apow_kernel, cudaFuncAttributeMaxDynamicSharedMemorySize, APSMEM);
    cudaFuncSetAttribute(stage2_kernel, cudaFuncAttributeMaxDynamicSharedMemorySize, S2SMEM);
    cudaFuncSetAttribute(outer_kernel, cudaFuncAttributeMaxDynamicSharedMemorySize, OSMEM);

    ksums_kernel<<<130, 32>>>(in_wb, in_bb);                          // 1 (+ctr reset)
    apow_kernel<<<64, 256, APSMEM>>>(A);                              // 2 (A^16 -> g_Q)
    seeds_kernel<<<1, 256>>>(C_ssm);                                  // 3
    chains_kernel<<<8, 256>>>(A, B_ssm, 0);                           // 4
    chains_kernel<<<8, 256>>>(A, B_ssm, 8);                           // 5
    g1mamba_kernel<<<256 + 2048, 256, G1SMEM>>>(x_kan, in_w1, in_b1,
                                                x_mamba, wm, out);    // 6 (profile target)
    gemm2_kernel<<<dim3(2, Bn / 64), 256>>>(in_w2, in_b2);            // 7
    stage2_kernel<<<dim3(2, Bn / 128), 256, S2SMEM>>>(x_kan, in_ww, in_bw); // 8
    outer_kernel<<<Bn / 128, 512, OSMEM>>>(out_w1, out_b1, out_w2, out_b2,
                                           out_ww, out_bw, out_wb, out_bb, wk, out); // 9
}